// round 6
// baseline (speedup 1.0000x reference)
#include <cuda_runtime.h>
#include <cstdint>

#define Nn 2048
#define Dd 1024
#define Hh 16
#define HD 64
#define NEMB 199
#define RAD 99

// ---------------- scratch (device globals; no allocation) ----------------
__device__ float g_q[Hh * Nn * HD];
__device__ float g_k[Hh * Nn * HD];        // pre-scaled by 1/8, bias included
__device__ float g_v[Hh * Nn * HD];
__device__ float g_ao[Nn * Dd];
__device__ uint32_t g_Ap[Nn * Dd];         // packed A frags (tf32 bits), 8MB
__device__ uint32_t g_Bp[3 * Dd * Dd];     // packed B frags (tf32 bits), 12MB

// ---------------- common helpers ------------------------------------------
__device__ __forceinline__ uint32_t f2tf(float f) {
    uint32_t u;
    asm("cvt.rna.tf32.f32 %0, %1;" : "=r"(u) : "f"(f));
    return u;
}
__device__ __forceinline__ uint32_t smem_u32(const void* p) {
    uint32_t a;
    asm("{ .reg .u64 t; cvta.to.shared.u64 t, %1; cvt.u32.u64 %0, t; }"
        : "=r"(a) : "l"(p));
    return a;
}
__device__ __forceinline__ void cp16(uint32_t dst, const void* src) {
    asm volatile("cp.async.cg.shared.global [%0], [%1], 16;" :: "r"(dst), "l"(src) : "memory");
}

#define MMA_TF32(d, a0, a1, a2, a3, b0, b1) \
    asm volatile( \
        "mma.sync.aligned.m16n8k8.row.col.f32.tf32.tf32.f32 " \
        "{%0,%1,%2,%3}, {%4,%5,%6,%7}, {%8,%9}, {%0,%1,%2,%3};" \
        : "+f"((d)[0]), "+f"((d)[1]), "+f"((d)[2]), "+f"((d)[3]) \
        : "r"(a0), "r"(a1), "r"(a2), "r"(a3), "r"(b0), "r"(b1))

#define MMA_TF32A(d, a, b) \
    asm volatile( \
        "mma.sync.aligned.m16n8k8.row.col.f32.tf32.tf32.f32 " \
        "{%0,%1,%2,%3}, {%4,%5,%6,%7}, {%8,%9}, {%0,%1,%2,%3};" \
        : "+f"((d)[0]), "+f"((d)[1]), "+f"((d)[2]), "+f"((d)[3]) \
        : "r"((a)[0]), "r"((a)[1]), "r"((a)[2]), "r"((a)[3]), \
          "r"((b)[0]), "r"((b)[1]))

// ---------------- pack kernels: fp32 -> fragment-ready tf32 ----------------
// A-frag pack: out[((mt*KS + ks)*32 + lane)] = 4 regs of m16k8 A-frag.
template <int SRCAO>
__global__ void __launch_bounds__(256) packA(const float* __restrict__ src,
                                             int rows, int K)
{
    const float* in = SRCAO ? (const float*)g_ao : src;
    int idx = blockIdx.x * 256 + threadIdx.x;
    int KS = K >> 3;
    int total = (rows >> 4) * KS * 32;
    if (idx >= total) return;
    int lane = idx & 31;
    int ks = (idx >> 5) % KS;
    int mt = (idx >> 5) / KS;
    int gid = lane >> 2, tig = lane & 3;
    int r0 = mt * 16 + gid, c0 = ks * 8 + tig;
    uint4 o;
    o.x = f2tf(in[(size_t)r0 * K + c0]);
    o.y = f2tf(in[(size_t)(r0 + 8) * K + c0]);
    o.z = f2tf(in[(size_t)r0 * K + c0 + 4]);
    o.w = f2tf(in[(size_t)(r0 + 8) * K + c0 + 4]);
    *(uint4*)&g_Ap[(size_t)idx * 4] = o;
}

// B-frag pack: out[((nt*KS + ks)*32 + lane)] = 2 regs of k8n8 B-frag.
__global__ void __launch_bounds__(256) packB(const float* __restrict__ src,
                                             int rowsB, int K)
{
    int idx = blockIdx.x * 256 + threadIdx.x;
    int KS = K >> 3;
    int total = (rowsB >> 3) * KS * 32;
    if (idx >= total) return;
    int lane = idx & 31;
    int ks = (idx >> 5) % KS;
    int nt = (idx >> 5) / KS;
    int gid = lane >> 2, tig = lane & 3;
    int n = nt * 8 + gid, c0 = ks * 8 + tig;
    uint2 o;
    o.x = f2tf(src[(size_t)n * K + c0]);
    o.y = f2tf(src[(size_t)n * K + c0 + 4]);
    *(uint2*)&g_Bp[(size_t)idx * 2] = o;
}

// ---------------- tf32 mma.sync GEMM on packed operands -------------------
// CTA tile 128x128, BK=32 (4 kslices/chunk), 2-stage cp.async.
#define GEMM_SMEM_BYTES 65536    // 2 stages x (16KB A + 16KB B)

template <int MODE>
__global__ void __launch_bounds__(256) mma_gemm(
    const float* __restrict__ bias, float* __restrict__ out, int K)
{
    extern __shared__ __align__(16) uint32_t smem[];
    uint32_t* sAm = smem;              // [2][4096]
    uint32_t* sBm = smem + 8192;       // [2][4096]
    const uint32_t sAu = smem_u32(sAm);
    const uint32_t sBu = smem_u32(sBm);

    const int t = threadIdx.x;
    const int KS = K >> 3;
    const int m0 = blockIdx.y * 128;
    const int n0 = blockIdx.x * 128;
    const int w = t >> 5, lane = t & 31;
    const int wy = w >> 2, wx = w & 3;
    const int gid = lane >> 2, tig = lane & 3;

    const uint32_t* Abase = g_Ap + (size_t)(blockIdx.y * 8) * KS * 128;
    const uint32_t* Bbase = g_Bp + (size_t)(blockIdx.x * 16) * KS * 64;

    float acc[4][4][4];
#pragma unroll
    for (int mi = 0; mi < 4; mi++)
#pragma unroll
        for (int ni = 0; ni < 4; ni++)
#pragma unroll
            for (int j = 0; j < 4; j++) acc[mi][ni][j] = 0.f;

    const int nc = K / 32;

    auto load_chunk = [&](int c, int s) {
        uint32_t ab = sAu + (uint32_t)s * 16384u;
        uint32_t bb = sBu + (uint32_t)s * 16384u;
#pragma unroll
        for (int q = 0; q < 4; q++) {
            int i4 = t + q * 256;                  // float4 index 0..1023
            int mt = i4 >> 7, rema = (i4 & 127) << 2;
            cp16(ab + (uint32_t)i4 * 16,
                 Abase + (size_t)mt * KS * 128 + c * 512 + rema);
            int nt = i4 >> 6, remb = (i4 & 63) << 2;
            cp16(bb + (uint32_t)i4 * 16,
                 Bbase + (size_t)nt * KS * 64 + c * 256 + remb);
        }
    };

    load_chunk(0, 0);
    asm volatile("cp.async.commit_group;" ::: "memory");

    for (int c = 0; c < nc; ++c) {
        int s = c & 1;
        if (c + 1 < nc) {
            load_chunk(c + 1, s ^ 1);
            asm volatile("cp.async.commit_group;" ::: "memory");
            asm volatile("cp.async.wait_group 1;" ::: "memory");
        } else {
            asm volatile("cp.async.wait_group 0;" ::: "memory");
        }
        __syncthreads();

        const uint32_t* As = sAm + s * 4096;
        const uint32_t* Bs = sBm + s * 4096;
#pragma unroll
        for (int ksp = 0; ksp < 4; ksp++) {
            uint4 af[4];
            uint2 bf[4];
#pragma unroll
            for (int mi = 0; mi < 4; mi++)
                af[mi] = *(const uint4*)&As[(((wy * 4 + mi) * 4 + ksp) << 7) + (lane << 2)];
#pragma unroll
            for (int ni = 0; ni < 4; ni++)
                bf[ni] = *(const uint2*)&Bs[(((wx * 4 + ni) * 4 + ksp) << 6) + (lane << 1)];
#pragma unroll
            for (int mi = 0; mi < 4; mi++)
#pragma unroll
                for (int ni = 0; ni < 4; ni++)
                    MMA_TF32(acc[mi][ni], af[mi].x, af[mi].y, af[mi].z, af[mi].w,
                             bf[ni].x, bf[ni].y);
        }
        __syncthreads();
    }

#pragma unroll
    for (int mi = 0; mi < 4; mi++) {
        int r0 = m0 + wy * 64 + mi * 16 + gid;
#pragma unroll
        for (int ni = 0; ni < 4; ni++) {
            int feat = n0 + wx * 32 + ni * 8 + 2 * tig;
            float2 bb = *(const float2*)&bias[feat];
            if (MODE == 0) {
                int sec = feat >> 10, hm = feat & 1023;
                float* p = (sec == 0) ? g_q : ((sec == 1) ? g_k : g_v);
                float sc = (sec == 1) ? 0.125f : 1.0f;
                int h = hm >> 6, d = hm & 63;
                float2 v0 = make_float2((acc[mi][ni][0] + bb.x) * sc,
                                        (acc[mi][ni][1] + bb.y) * sc);
                float2 v1 = make_float2((acc[mi][ni][2] + bb.x) * sc,
                                        (acc[mi][ni][3] + bb.y) * sc);
                *(float2*)&p[((h * Nn + r0) << 6) + d] = v0;
                *(float2*)&p[((h * Nn + r0 + 8) << 6) + d] = v1;
            } else {
                float2 v0 = make_float2(acc[mi][ni][0] + bb.x, acc[mi][ni][1] + bb.y);
                float2 v1 = make_float2(acc[mi][ni][2] + bb.x, acc[mi][ni][3] + bb.y);
                *(float2*)&out[(size_t)r0 * Dd + feat] = v0;
                *(float2*)&out[(size_t)(r0 + 8) * Dd + feat] = v1;
            }
        }
    }
}

// ---------------- fused banded attention + pos logits (tf32 mma) ----------
#define BP 68
#define SSP 460
#define SQ_F (32 * BP)
#define SB_F (448 * BP)
#define SS_F (32 * SSP)
#define ATTN_SMEM_BYTES ((SQ_F + SB_F + SS_F) * 4)

__global__ void __launch_bounds__(256) attn_kernel(const float* __restrict__ rel_emb)
{
    extern __shared__ __align__(16) float sm[];
    float* sQ = sm;
    float* sB = sm + SQ_F;
    float* sS = sm + SQ_F + SB_F;

    const int h = blockIdx.y;
    const int i0 = blockIdx.x * 32;
    const int jlo = i0 - RAD;
    const int t = threadIdx.x;
    const int w = t >> 5, lane = t & 31;
    const int gid = lane >> 2, tig = lane & 3;

    for (int idx = t; idx < 32 * 16; idx += 256) {
        int qi = idx >> 4, d4 = (idx & 15) << 2;
        *(float4*)&sQ[qi * BP + d4] =
            *(const float4*)&g_q[((h * Nn + i0 + qi) << 6) + d4];
    }
    for (int idx = t; idx < 240 * 16; idx += 256) {
        int jj = idx >> 4, d4 = (idx & 15) << 2;
        int j = jlo + jj;
        float4 v = make_float4(0.f, 0.f, 0.f, 0.f);
        if (j >= 0 && j < Nn)
            v = *(const float4*)&g_k[((h * Nn + j) << 6) + d4];
        *(float4*)&sB[jj * BP + d4] = v;
    }
    const float* E = rel_emb + (size_t)h * NEMB * HD;
    for (int idx = t; idx < 208 * 16; idx += 256) {
        int r = idx >> 4, d4 = (idx & 15) << 2;
        float4 v = make_float4(0.f, 0.f, 0.f, 0.f);
        if (r < NEMB) v = *(const float4*)&E[r * HD + d4];
        *(float4*)&sB[(240 + r) * BP + d4] = v;
    }
    __syncthreads();

    {
        float acc[2][7][4];
#pragma unroll
        for (int mi = 0; mi < 2; mi++)
#pragma unroll
            for (int f = 0; f < 7; f++)
#pragma unroll
                for (int j = 0; j < 4; j++) acc[mi][f][j] = 0.f;

#pragma unroll
        for (int ks = 0; ks < 8; ks++) {
            int kb = ks * 8 + tig;
            uint32_t af[2][4];
#pragma unroll
            for (int mi = 0; mi < 2; mi++) {
                af[mi][0] = f2tf(sQ[(mi * 16 + gid) * BP + kb]);
                af[mi][1] = f2tf(sQ[(mi * 16 + gid + 8) * BP + kb]);
                af[mi][2] = f2tf(sQ[(mi * 16 + gid) * BP + kb + 4]);
                af[mi][3] = f2tf(sQ[(mi * 16 + gid + 8) * BP + kb + 4]);
            }
#pragma unroll
            for (int f = 0; f < 7; f++) {
                int nb = (w * 7 + f) * 8;
                uint32_t bf[2];
                bf[0] = f2tf(sB[(nb + gid) * BP + kb]);
                bf[1] = f2tf(sB[(nb + gid) * BP + kb + 4]);
                MMA_TF32A(acc[0][f], af[0], bf);
                MMA_TF32A(acc[1][f], af[1], bf);
            }
        }
#pragma unroll
        for (int mi = 0; mi < 2; mi++) {
            int r0 = mi * 16 + gid;
#pragma unroll
            for (int f = 0; f < 7; f++) {
                int col = (w * 7 + f) * 8 + 2 * tig;
                *(float2*)&sS[r0 * SSP + col] = make_float2(acc[mi][f][0], acc[mi][f][1]);
                *(float2*)&sS[(r0 + 8) * SSP + col] = make_float2(acc[mi][f][2], acc[mi][f][3]);
            }
        }
    }
    __syncthreads();

    for (int idx = t; idx < 240 * 16; idx += 256) {
        int jj = idx >> 4, d4 = (idx & 15) << 2;
        int j = jlo + jj;
        float4 v = make_float4(0.f, 0.f, 0.f, 0.f);
        if (j >= 0 && j < Nn)
            v = *(const float4*)&g_v[((h * Nn + j) << 6) + d4];
        *(float4*)&sB[jj * BP + d4] = v;
    }

    {
#pragma unroll
        for (int p = 0; p < 4; p++) {
            int qi = w * 4 + p;
            int i = i0 + qi;
            float v[7];
#pragma unroll
            for (int u = 0; u < 7; u++) {
                int r = lane + u * 32;
                float val = -1e30f;
                if (r < NEMB) {
                    int j = i - RAD + r;
                    if (j >= 0 && j < Nn)
                        val = sS[qi * SSP + qi + r] + sS[qi * SSP + 240 + r];
                }
                v[u] = val;
            }
            __syncwarp();
            float mx = v[0];
#pragma unroll
            for (int u = 1; u < 7; u++) mx = fmaxf(mx, v[u]);
#pragma unroll
            for (int off = 16; off; off >>= 1) mx = fmaxf(mx, __shfl_xor_sync(0xffffffffu, mx, off));
            float e[7], s = 0.f;
#pragma unroll
            for (int u = 0; u < 7; u++) {
                e[u] = (v[u] > -1e29f) ? __expf(v[u] - mx) : 0.f;
                s += e[u];
            }
#pragma unroll
            for (int off = 16; off; off >>= 1) s += __shfl_xor_sync(0xffffffffu, s, off);
            float inv = 1.f / s;
            for (int c = lane; c < 240; c += 32) sS[qi * SSP + c] = 0.f;
            __syncwarp();
#pragma unroll
            for (int u = 0; u < 7; u++) {
                int r = lane + u * 32;
                if (r < NEMB && e[u] != 0.f) sS[qi * SSP + qi + r] = e[u] * inv;
            }
            __syncwarp();
        }
    }
    __syncthreads();

    {
        float acc[2][4];
#pragma unroll
        for (int mi = 0; mi < 2; mi++)
#pragma unroll
            for (int j = 0; j < 4; j++) acc[mi][j] = 0.f;

        int nd = w * 8 + gid;
#pragma unroll
        for (int ks = 0; ks < 30; ks++) {
            int kb = ks * 8 + tig;
            uint32_t af[2][4];
#pragma unroll
            for (int mi = 0; mi < 2; mi++) {
                af[mi][0] = f2tf(sS[(mi * 16 + gid) * SSP + kb]);
                af[mi][1] = f2tf(sS[(mi * 16 + gid + 8) * SSP + kb]);
                af[mi][2] = f2tf(sS[(mi * 16 + gid) * SSP + kb + 4]);
                af[mi][3] = f2tf(sS[(mi * 16 + gid + 8) * SSP + kb + 4]);
            }
            uint32_t bf[2];
            bf[0] = f2tf(sB[kb * BP + nd]);
            bf[1] = f2tf(sB[(kb + 4) * BP + nd]);
            MMA_TF32A(acc[0], af[0], bf);
            MMA_TF32A(acc[1], af[1], bf);
        }
#pragma unroll
        for (int mi = 0; mi < 2; mi++) {
            int row = mi * 16 + gid;
            int dcol = h * 64 + w * 8 + 2 * tig;
            *(float2*)&g_ao[(size_t)(i0 + row) * Dd + dcol] =
                make_float2(acc[mi][0], acc[mi][1]);
            *(float2*)&g_ao[(size_t)(i0 + row + 8) * Dd + dcol] =
                make_float2(acc[mi][2], acc[mi][3]);
        }
    }
}

// ---------------- launcher ------------------------------------------------
extern "C" void kernel_launch(void* const* d_in, const int* in_sizes, int n_in,
                              void* d_out, int out_size)
{
    (void)in_sizes; (void)n_in; (void)out_size;
    const float* x      = (const float*)d_in[0];
    const float* qkv_w  = (const float*)d_in[1];
    const float* qkv_b  = (const float*)d_in[2];
    const float* proj_w = (const float*)d_in[3];
    const float* proj_b = (const float*)d_in[4];
    const float* rel    = (const float*)d_in[5];
    float* out = (float*)d_out;

    cudaFuncSetAttribute(mma_gemm<0>, cudaFuncAttributeMaxDynamicSharedMemorySize,
                         GEMM_SMEM_BYTES);
    cudaFuncSetAttribute(mma_gemm<1>, cudaFuncAttributeMaxDynamicSharedMemorySize,
                         GEMM_SMEM_BYTES);
    cudaFuncSetAttribute(attn_kernel, cudaFuncAttributeMaxDynamicSharedMemorySize,
                         ATTN_SMEM_BYTES);

    // 1) pack x (A-frags) and qkv_w (B-frags)
    packA<0><<<(Nn / 16) * (Dd / 8) * 32 / 256, 256>>>(x, Nn, Dd);
    packB<<<(3 * Dd / 8) * (Dd / 8) * 32 / 256, 256>>>(qkv_w, 3 * Dd, Dd);
    // 2) QKV GEMM: scatter q / k(scaled) / v
    mma_gemm<0><<<dim3(3 * Dd / 128, Nn / 128), 256, GEMM_SMEM_BYTES>>>(qkv_b,
                                                                        nullptr, Dd);
    // 3) fused pos + banded attention -> g_ao
    attn_kernel<<<dim3(Nn / 32, Hh), 256, ATTN_SMEM_BYTES>>>(rel);
    // 4) pack g_ao (A-frags) and proj_w (B-frags)
    packA<1><<<(Nn / 16) * (Dd / 8) * 32 / 256, 256>>>(nullptr, Nn, Dd);
    packB<<<(Dd / 8) * (Dd / 8) * 32 / 256, 256>>>(proj_w, Dd, Dd);
    // 5) output projection -> d_out
    mma_gemm<1><<<dim3(Dd / 128, Nn / 128), 256, GEMM_SMEM_BYTES>>>(proj_b, out, Dd);
}

// round 7
// speedup vs baseline: 1.1700x; 1.1700x over previous
#include <cuda_runtime.h>
#include <cstdint>

#define Nn 2048
#define Dd 1024
#define Hh 16
#define HD 64
#define NEMB 199
#define RAD 99

// ---------------- scratch (device globals; no allocation) ----------------
__device__ float g_q[Hh * Nn * HD];
__device__ float g_k[Hh * Nn * HD];        // pre-scaled by 1/8, bias included
__device__ float g_v[Hh * Nn * HD];
__device__ float g_ao[Nn * Dd];
__device__ uint32_t g_Ap[Nn * Dd];         // packed A frags (tf32 bits)
__device__ uint32_t g_Bp[3 * Dd * Dd];     // packed B frags (tf32 bits)

// ---------------- common helpers ------------------------------------------
__device__ __forceinline__ uint32_t f2tf(float f) {
    uint32_t u;
    asm("cvt.rna.tf32.f32 %0, %1;" : "=r"(u) : "f"(f));
    return u;
}
__device__ __forceinline__ float f2tff(float f) {
    return __uint_as_float(f2tf(f));
}
__device__ __forceinline__ uint32_t smem_u32(const void* p) {
    uint32_t a;
    asm("{ .reg .u64 t; cvta.to.shared.u64 t, %1; cvt.u32.u64 %0, t; }"
        : "=r"(a) : "l"(p));
    return a;
}
__device__ __forceinline__ void cp16(uint32_t dst, const void* src) {
    asm volatile("cp.async.cg.shared.global [%0], [%1], 16;" :: "r"(dst), "l"(src) : "memory");
}

#define MMA_TF32(d, a0, a1, a2, a3, b0, b1) \
    asm volatile( \
        "mma.sync.aligned.m16n8k8.row.col.f32.tf32.tf32.f32 " \
        "{%0,%1,%2,%3}, {%4,%5,%6,%7}, {%8,%9}, {%0,%1,%2,%3};" \
        : "+f"((d)[0]), "+f"((d)[1]), "+f"((d)[2]), "+f"((d)[3]) \
        : "r"(a0), "r"(a1), "r"(a2), "r"(a3), "r"(b0), "r"(b1))

// ---------------- pack kernels: fp32 -> fragment-ready tf32 ----------------
template <int SRCAO>
__global__ void __launch_bounds__(256) packA(const float* __restrict__ src,
                                             int rows, int K)
{
    const float* in = SRCAO ? (const float*)g_ao : src;
    int idx = blockIdx.x * 256 + threadIdx.x;
    int KS = K >> 3;
    int total = (rows >> 4) * KS * 32;
    if (idx >= total) return;
    int lane = idx & 31;
    int ks = (idx >> 5) % KS;
    int mt = (idx >> 5) / KS;
    int gid = lane >> 2, tig = lane & 3;
    int r0 = mt * 16 + gid, c0 = ks * 8 + tig;
    uint4 o;
    o.x = f2tf(in[(size_t)r0 * K + c0]);
    o.y = f2tf(in[(size_t)(r0 + 8) * K + c0]);
    o.z = f2tf(in[(size_t)r0 * K + c0 + 4]);
    o.w = f2tf(in[(size_t)(r0 + 8) * K + c0 + 4]);
    *(uint4*)&g_Ap[(size_t)idx * 4] = o;
}

__global__ void __launch_bounds__(256) packB(const float* __restrict__ src,
                                             int rowsB, int K)
{
    int idx = blockIdx.x * 256 + threadIdx.x;
    int KS = K >> 3;
    int total = (rowsB >> 3) * KS * 32;
    if (idx >= total) return;
    int lane = idx & 31;
    int ks = (idx >> 5) % KS;
    int nt = (idx >> 5) / KS;
    int gid = lane >> 2, tig = lane & 3;
    int n = nt * 8 + gid, c0 = ks * 8 + tig;
    uint2 o;
    o.x = f2tf(src[(size_t)n * K + c0]);
    o.y = f2tf(src[(size_t)n * K + c0 + 4]);
    *(uint2*)&g_Bp[(size_t)idx * 2] = o;
}

// ---------------- tf32 mma.sync GEMM on packed operands -------------------
#define GEMM_SMEM_BYTES 65536

template <int MODE>
__global__ void __launch_bounds__(256) mma_gemm(
    const float* __restrict__ bias, float* __restrict__ out, int K)
{
    extern __shared__ __align__(16) uint32_t smem[];
    uint32_t* sAm = smem;
    uint32_t* sBm = smem + 8192;
    const uint32_t sAu = smem_u32(sAm);
    const uint32_t sBu = smem_u32(sBm);

    const int t = threadIdx.x;
    const int KS = K >> 3;
    const int m0 = blockIdx.y * 128;
    const int n0 = blockIdx.x * 128;
    const int w = t >> 5, lane = t & 31;
    const int wy = w >> 2, wx = w & 3;
    const int gid = lane >> 2, tig = lane & 3;

    const uint32_t* Abase = g_Ap + (size_t)(blockIdx.y * 8) * KS * 128;
    const uint32_t* Bbase = g_Bp + (size_t)(blockIdx.x * 16) * KS * 64;

    float acc[4][4][4];
#pragma unroll
    for (int mi = 0; mi < 4; mi++)
#pragma unroll
        for (int ni = 0; ni < 4; ni++)
#pragma unroll
            for (int j = 0; j < 4; j++) acc[mi][ni][j] = 0.f;

    const int nc = K / 32;

    auto load_chunk = [&](int c, int s) {
        uint32_t ab = sAu + (uint32_t)s * 16384u;
        uint32_t bb = sBu + (uint32_t)s * 16384u;
#pragma unroll
        for (int q = 0; q < 4; q++) {
            int i4 = t + q * 256;
            int mt = i4 >> 7, rema = (i4 & 127) << 2;
            cp16(ab + (uint32_t)i4 * 16,
                 Abase + (size_t)mt * KS * 128 + c * 512 + rema);
            int nt = i4 >> 6, remb = (i4 & 63) << 2;
            cp16(bb + (uint32_t)i4 * 16,
                 Bbase + (size_t)nt * KS * 64 + c * 256 + remb);
        }
    };

    load_chunk(0, 0);
    asm volatile("cp.async.commit_group;" ::: "memory");

    for (int c = 0; c < nc; ++c) {
        int s = c & 1;
        if (c + 1 < nc) {
            load_chunk(c + 1, s ^ 1);
            asm volatile("cp.async.commit_group;" ::: "memory");
            asm volatile("cp.async.wait_group 1;" ::: "memory");
        } else {
            asm volatile("cp.async.wait_group 0;" ::: "memory");
        }
        __syncthreads();

        const uint32_t* As = sAm + s * 4096;
        const uint32_t* Bs = sBm + s * 4096;
#pragma unroll
        for (int ksp = 0; ksp < 4; ksp++) {
            uint4 af[4];
            uint2 bf[4];
#pragma unroll
            for (int mi = 0; mi < 4; mi++)
                af[mi] = *(const uint4*)&As[(((wy * 4 + mi) * 4 + ksp) << 7) + (lane << 2)];
#pragma unroll
            for (int ni = 0; ni < 4; ni++)
                bf[ni] = *(const uint2*)&Bs[(((wx * 4 + ni) * 4 + ksp) << 6) + (lane << 1)];
#pragma unroll
            for (int mi = 0; mi < 4; mi++)
#pragma unroll
                for (int ni = 0; ni < 4; ni++)
                    MMA_TF32(acc[mi][ni], af[mi].x, af[mi].y, af[mi].z, af[mi].w,
                             bf[ni].x, bf[ni].y);
        }
        __syncthreads();
    }

#pragma unroll
    for (int mi = 0; mi < 4; mi++) {
        int r0 = m0 + wy * 64 + mi * 16 + gid;
#pragma unroll
        for (int ni = 0; ni < 4; ni++) {
            int feat = n0 + wx * 32 + ni * 8 + 2 * tig;
            float2 bb = *(const float2*)&bias[feat];
            if (MODE == 0) {
                int sec = feat >> 10, hm = feat & 1023;
                float* p = (sec == 0) ? g_q : ((sec == 1) ? g_k : g_v);
                float sc = (sec == 1) ? 0.125f : 1.0f;
                int h = hm >> 6, d = hm & 63;
                float2 v0 = make_float2((acc[mi][ni][0] + bb.x) * sc,
                                        (acc[mi][ni][1] + bb.y) * sc);
                float2 v1 = make_float2((acc[mi][ni][2] + bb.x) * sc,
                                        (acc[mi][ni][3] + bb.y) * sc);
                *(float2*)&p[((h * Nn + r0) << 6) + d] = v0;
                *(float2*)&p[((h * Nn + r0 + 8) << 6) + d] = v1;
            } else {
                float2 v0 = make_float2(acc[mi][ni][0] + bb.x, acc[mi][ni][1] + bb.y);
                float2 v1 = make_float2(acc[mi][ni][2] + bb.x, acc[mi][ni][3] + bb.y);
                *(float2*)&out[(size_t)r0 * Dd + feat] = v0;
                *(float2*)&out[(size_t)(r0 + 8) * Dd + feat] = v1;
            }
        }
    }
}

// ---------------- fused banded attention + pos logits, 64q/512t ----------
// Block = (64-query tile, head), 16 warps. Single band buffer sequenced
// E(224) -> K(288) -> V(288). All smem operands stored as tf32 bits.
#define QT 64
#define BND 288          // padded band rows (jj used: 0..261)
#define ERWS 224         // padded rel_emb rows (199 valid)
#define BP 68            // band/Q row pitch
#define SSP 516          // sS row pitch: 288 band + 224 pos + 4 pad
#define SQ_F (QT * BP)                 // 4352
#define SB_F (BND * BP)                // 19584
#define SS_F (QT * SSP)                // 33024
#define ATTN_SMEM_BYTES ((SQ_F + SB_F + SS_F) * 4)   // 227840

__global__ void __launch_bounds__(512) attn_kernel(const float* __restrict__ rel_emb)
{
    extern __shared__ __align__(16) float sm[];
    float* sQ = sm;                    // [64][BP]  (tf32 bits)
    float* sB = sm + SQ_F;             // [288][BP] (tf32 bits): E -> K -> V
    float* sS = sm + SQ_F + SB_F;      // [64][SSP]: cols 0..287 Sqk->P, 288..511 Spos

    const int h = blockIdx.y;
    const int i0 = blockIdx.x * QT;
    const int jlo = i0 - RAD;
    const int t = threadIdx.x;
    const int w = t >> 5, lane = t & 31;
    const int gid = lane >> 2, tig = lane & 3;
    const int mw = w & 3, nw = w >> 2;    // 4 m-groups x 4 n-groups

    // ---- load Q (64x64, tf32) and E (224 rows, tf32, zero-padded) ----
    for (int idx = t; idx < QT * 16; idx += 512) {
        int qi = idx >> 4, d4 = (idx & 15) << 2;
        float4 v = *(const float4*)&g_q[((h * Nn + i0 + qi) << 6) + d4];
        *(float4*)&sQ[qi * BP + d4] = make_float4(f2tff(v.x), f2tff(v.y),
                                                  f2tff(v.z), f2tff(v.w));
    }
    const float* E = rel_emb + (size_t)h * NEMB * HD;
    for (int idx = t; idx < ERWS * 16; idx += 512) {
        int r = idx >> 4, d4 = (idx & 15) << 2;
        float4 o = make_float4(0.f, 0.f, 0.f, 0.f);
        if (r < NEMB) {
            float4 v = *(const float4*)&E[r * HD + d4];
            o = make_float4(f2tff(v.x), f2tff(v.y), f2tff(v.z), f2tff(v.w));
        }
        *(float4*)&sB[r * BP + d4] = o;
    }
    __syncthreads();

    // ---- Spos = Q @ E^T (64x224): warp (mw,nw) -> mtile mw, frags nw*7.. ----
    {
        float acc[7][4];
#pragma unroll
        for (int f = 0; f < 7; f++)
#pragma unroll
            for (int j = 0; j < 4; j++) acc[f][j] = 0.f;
#pragma unroll
        for (int ks = 0; ks < 8; ks++) {
            int kb = ks * 8 + tig;
            uint32_t a0 = __float_as_uint(sQ[(mw * 16 + gid) * BP + kb]);
            uint32_t a1 = __float_as_uint(sQ[(mw * 16 + gid + 8) * BP + kb]);
            uint32_t a2 = __float_as_uint(sQ[(mw * 16 + gid) * BP + kb + 4]);
            uint32_t a3 = __float_as_uint(sQ[(mw * 16 + gid + 8) * BP + kb + 4]);
#pragma unroll
            for (int f = 0; f < 7; f++) {
                int nb = (nw * 7 + f) * 8;
                uint32_t b0 = __float_as_uint(sB[(nb + gid) * BP + kb]);
                uint32_t b1 = __float_as_uint(sB[(nb + gid) * BP + kb + 4]);
                MMA_TF32(acc[f], a0, a1, a2, a3, b0, b1);
            }
        }
        int r0 = mw * 16 + gid;
#pragma unroll
        for (int f = 0; f < 7; f++) {
            int col = BND + (nw * 7 + f) * 8 + 2 * tig;
            *(float2*)&sS[r0 * SSP + col] = make_float2(acc[f][0], acc[f][1]);
            *(float2*)&sS[(r0 + 8) * SSP + col] = make_float2(acc[f][2], acc[f][3]);
        }
    }
    __syncthreads();

    // ---- overwrite sB with K band (288 rows, tf32, zero OOB) ----
    for (int idx = t; idx < BND * 16; idx += 512) {
        int jj = idx >> 4, d4 = (idx & 15) << 2;
        int j = jlo + jj;
        float4 o = make_float4(0.f, 0.f, 0.f, 0.f);
        if (j >= 0 && j < Nn) {
            float4 v = *(const float4*)&g_k[((h * Nn + j) << 6) + d4];
            o = make_float4(f2tff(v.x), f2tff(v.y), f2tff(v.z), f2tff(v.w));
        }
        *(float4*)&sB[jj * BP + d4] = o;
    }
    __syncthreads();

    // ---- Sqk = Q @ K^T (64x288): warp (mw,nw) -> frags nw*9.. (9 each) ----
    {
        float acc[9][4];
#pragma unroll
        for (int f = 0; f < 9; f++)
#pragma unroll
            for (int j = 0; j < 4; j++) acc[f][j] = 0.f;
#pragma unroll
        for (int ks = 0; ks < 8; ks++) {
            int kb = ks * 8 + tig;
            uint32_t a0 = __float_as_uint(sQ[(mw * 16 + gid) * BP + kb]);
            uint32_t a1 = __float_as_uint(sQ[(mw * 16 + gid + 8) * BP + kb]);
            uint32_t a2 = __float_as_uint(sQ[(mw * 16 + gid) * BP + kb + 4]);
            uint32_t a3 = __float_as_uint(sQ[(mw * 16 + gid + 8) * BP + kb + 4]);
#pragma unroll
            for (int f = 0; f < 9; f++) {
                int nb = (nw * 9 + f) * 8;
                uint32_t b0 = __float_as_uint(sB[(nb + gid) * BP + kb]);
                uint32_t b1 = __float_as_uint(sB[(nb + gid) * BP + kb + 4]);
                MMA_TF32(acc[f], a0, a1, a2, a3, b0, b1);
            }
        }
        int r0 = mw * 16 + gid;
#pragma unroll
        for (int f = 0; f < 9; f++) {
            int col = (nw * 9 + f) * 8 + 2 * tig;
            *(float2*)&sS[r0 * SSP + col] = make_float2(acc[f][0], acc[f][1]);
            *(float2*)&sS[(r0 + 8) * SSP + col] = make_float2(acc[f][2], acc[f][3]);
        }
    }
    __syncthreads();

    // ---- overwrite sB with V band (tf32); then softmax (independent region) --
    for (int idx = t; idx < BND * 16; idx += 512) {
        int jj = idx >> 4, d4 = (idx & 15) << 2;
        int j = jlo + jj;
        float4 o = make_float4(0.f, 0.f, 0.f, 0.f);
        if (j >= 0 && j < Nn) {
            float4 v = *(const float4*)&g_v[((h * Nn + j) << 6) + d4];
            o = make_float4(f2tff(v.x), f2tff(v.y), f2tff(v.z), f2tff(v.w));
        }
        *(float4*)&sB[jj * BP + d4] = o;
    }

    // ---- banded softmax: warp w owns rows w*4..w*4+3; writes P as tf32 ----
    {
#pragma unroll
        for (int p = 0; p < 4; p++) {
            int qi = w * 4 + p;
            int i = i0 + qi;
            float v[7];
#pragma unroll
            for (int u = 0; u < 7; u++) {
                int r = lane + u * 32;
                float val = -1e30f;
                if (r < NEMB) {
                    int j = i - RAD + r;
                    if (j >= 0 && j < Nn)
                        val = sS[qi * SSP + qi + r] + sS[qi * SSP + BND + r];
                }
                v[u] = val;
            }
            __syncwarp();
            float mx = v[0];
#pragma unroll
            for (int u = 1; u < 7; u++) mx = fmaxf(mx, v[u]);
#pragma unroll
            for (int off = 16; off; off >>= 1) mx = fmaxf(mx, __shfl_xor_sync(0xffffffffu, mx, off));
            float e[7], s = 0.f;
#pragma unroll
            for (int u = 0; u < 7; u++) {
                e[u] = (v[u] > -1e29f) ? __expf(v[u] - mx) : 0.f;
                s += e[u];
            }
#pragma unroll
            for (int off = 16; off; off >>= 1) s += __shfl_xor_sync(0xffffffffu, s, off);
            float inv = 1.f / s;
            for (int c = lane; c < BND; c += 32) sS[qi * SSP + c] = 0.f;
            __syncwarp();
#pragma unroll
            for (int u = 0; u < 7; u++) {
                int r = lane + u * 32;
                if (r < NEMB && e[u] != 0.f)
                    sS[qi * SSP + qi + r] = f2tff(e[u] * inv);
            }
            __syncwarp();
        }
    }
    __syncthreads();

    // ---- O = P(64x272) @ V(272x64): warp (mw,nw) -> mtile mw, 2 d-frags ----
    {
        float acc[2][4];
#pragma unroll
        for (int ff = 0; ff < 2; ff++)
#pragma unroll
            for (int j = 0; j < 4; j++) acc[ff][j] = 0.f;

#pragma unroll
        for (int ks = 0; ks < 34; ks++) {     // P cols >= 272 are zero
            int kb = ks * 8 + tig;
            uint32_t a0 = __float_as_uint(sS[(mw * 16 + gid) * SSP + kb]);
            uint32_t a1 = __float_as_uint(sS[(mw * 16 + gid + 8) * SSP + kb]);
            uint32_t a2 = __float_as_uint(sS[(mw * 16 + gid) * SSP + kb + 4]);
            uint32_t a3 = __float_as_uint(sS[(mw * 16 + gid + 8) * SSP + kb + 4]);
#pragma unroll
            for (int ff = 0; ff < 2; ff++) {
                int nd = (nw * 2 + ff) * 8 + gid;
                uint32_t b0 = __float_as_uint(sB[kb * BP + nd]);
                uint32_t b1 = __float_as_uint(sB[(kb + 4) * BP + nd]);
                MMA_TF32(acc[ff], a0, a1, a2, a3, b0, b1);
            }
        }
        int row = mw * 16 + gid;
#pragma unroll
        for (int ff = 0; ff < 2; ff++) {
            int dcol = h * 64 + (nw * 2 + ff) * 8 + 2 * tig;
            *(float2*)&g_ao[(size_t)(i0 + row) * Dd + dcol] =
                make_float2(acc[ff][0], acc[ff][1]);
            *(float2*)&g_ao[(size_t)(i0 + row + 8) * Dd + dcol] =
                make_float2(acc[ff][2], acc[ff][3]);
        }
    }
}

// ---------------- launcher ------------------------------------------------
extern "C" void kernel_launch(void* const* d_in, const int* in_sizes, int n_in,
                              void* d_out, int out_size)
{
    (void)in_sizes; (void)n_in; (void)out_size;
    const float* x      = (const float*)d_in[0];
    const float* qkv_w  = (const float*)d_in[1];
    const float* qkv_b  = (const float*)d_in[2];
    const float* proj_w = (const float*)d_in[3];
    const float* proj_b = (const float*)d_in[4];
    const float* rel    = (const float*)d_in[5];
    float* out = (float*)d_out;

    cudaFuncSetAttribute(mma_gemm<0>, cudaFuncAttributeMaxDynamicSharedMemorySize,
                         GEMM_SMEM_BYTES);
    cudaFuncSetAttribute(mma_gemm<1>, cudaFuncAttributeMaxDynamicSharedMemorySize,
                         GEMM_SMEM_BYTES);
    cudaFuncSetAttribute(attn_kernel, cudaFuncAttributeMaxDynamicSharedMemorySize,
                         ATTN_SMEM_BYTES);

    // 1) pack x (A-frags) and qkv_w (B-frags)
    packA<0><<<(Nn / 16) * (Dd / 8) * 32 / 256, 256>>>(x, Nn, Dd);
    packB<<<(3 * Dd / 8) * (Dd / 8) * 32 / 256, 256>>>(qkv_w, 3 * Dd, Dd);
    // 2) QKV GEMM: scatter q / k(scaled) / v
    mma_gemm<0><<<dim3(3 * Dd / 128, Nn / 128), 256, GEMM_SMEM_BYTES>>>(qkv_b,
                                                                        nullptr, Dd);
    // 3) fused pos + banded attention (64q/512t) -> g_ao
    attn_kernel<<<dim3(Nn / QT, Hh), 512, ATTN_SMEM_BYTES>>>(rel);
    // 4) pack g_ao (A-frags) and proj_w (B-frags)
    packA<1><<<(Nn / 16) * (Dd / 8) * 32 / 256, 256>>>(nullptr, Nn, Dd);
    packB<<<(Dd / 8) * (Dd / 8) * 32 / 256, 256>>>(proj_w, Dd, Dd);
    // 5) output projection -> d_out
    mma_gemm<1><<<dim3(Dd / 128, Nn / 128), 256, GEMM_SMEM_BYTES>>>(proj_b, out, Dd);
}

// round 8
// speedup vs baseline: 1.2416x; 1.0612x over previous
#include <cuda_runtime.h>
#include <cstdint>

#define Nn 2048
#define Dd 1024
#define Hh 16
#define HD 64
#define NEMB 199
#define RAD 99

// ---------------- scratch (device globals; no allocation) ----------------
__device__ float g_q[Hh * Nn * HD];
__device__ float g_k[Hh * Nn * HD];        // pre-scaled by 1/8, bias included
__device__ float g_v[Hh * Nn * HD];
__device__ float g_ao[Nn * Dd];
__device__ uint32_t g_Ap[Nn * Dd];         // packed A frags (tf32 bits)
__device__ uint32_t g_Bp[3 * Dd * Dd];     // packed B frags (tf32 bits)

// ---------------- common helpers ------------------------------------------
__device__ __forceinline__ uint32_t f2tf(float f) {
    uint32_t u;
    asm("cvt.rna.tf32.f32 %0, %1;" : "=r"(u) : "f"(f));
    return u;
}
__device__ __forceinline__ float f2tff(float f) {
    return __uint_as_float(f2tf(f));
}
__device__ __forceinline__ uint32_t smem_u32(const void* p) {
    uint32_t a;
    asm("{ .reg .u64 t; cvta.to.shared.u64 t, %1; cvt.u32.u64 %0, t; }"
        : "=r"(a) : "l"(p));
    return a;
}
__device__ __forceinline__ void cp16(uint32_t dst, const void* src) {
    asm volatile("cp.async.cg.shared.global [%0], [%1], 16;" :: "r"(dst), "l"(src) : "memory");
}

#define MMA_TF32(d, a0, a1, a2, a3, b0, b1) \
    asm volatile( \
        "mma.sync.aligned.m16n8k8.row.col.f32.tf32.tf32.f32 " \
        "{%0,%1,%2,%3}, {%4,%5,%6,%7}, {%8,%9}, {%0,%1,%2,%3};" \
        : "+f"((d)[0]), "+f"((d)[1]), "+f"((d)[2]), "+f"((d)[3]) \
        : "r"(a0), "r"(a1), "r"(a2), "r"(a3), "r"(b0), "r"(b1))

// ---------------- pack kernels: fp32 -> fragment-ready tf32 ----------------
template <int SRCAO>
__global__ void __launch_bounds__(256) packA(const float* __restrict__ src,
                                             int rows, int K)
{
    const float* in = SRCAO ? (const float*)g_ao : src;
    int idx = blockIdx.x * 256 + threadIdx.x;
    int KS = K >> 3;
    int total = (rows >> 4) * KS * 32;
    if (idx >= total) return;
    int lane = idx & 31;
    int ks = (idx >> 5) % KS;
    int mt = (idx >> 5) / KS;
    int gid = lane >> 2, tig = lane & 3;
    int r0 = mt * 16 + gid, c0 = ks * 8 + tig;
    uint4 o;
    o.x = f2tf(in[(size_t)r0 * K + c0]);
    o.y = f2tf(in[(size_t)(r0 + 8) * K + c0]);
    o.z = f2tf(in[(size_t)r0 * K + c0 + 4]);
    o.w = f2tf(in[(size_t)(r0 + 8) * K + c0 + 4]);
    *(uint4*)&g_Ap[(size_t)idx * 4] = o;
}

__global__ void __launch_bounds__(256) packB(const float* __restrict__ src,
                                             int rowsB, int K)
{
    int idx = blockIdx.x * 256 + threadIdx.x;
    int KS = K >> 3;
    int total = (rowsB >> 3) * KS * 32;
    if (idx >= total) return;
    int lane = idx & 31;
    int ks = (idx >> 5) % KS;
    int nt = (idx >> 5) / KS;
    int gid = lane >> 2, tig = lane & 3;
    int n = nt * 8 + gid, c0 = ks * 8 + tig;
    uint2 o;
    o.x = f2tf(src[(size_t)n * K + c0]);
    o.y = f2tf(src[(size_t)n * K + c0 + 4]);
    *(uint2*)&g_Bp[(size_t)idx * 2] = o;
}

// ---------------- tf32 mma.sync GEMM, 3-stage cp.async --------------------
#define GEMM_SMEM_BYTES 98304    // 3 stages x (16KB A + 16KB B)

template <int MODE>
__global__ void __launch_bounds__(256) mma_gemm(
    const float* __restrict__ bias, float* __restrict__ out, int K)
{
    extern __shared__ __align__(16) uint32_t smem[];
    uint32_t* sAm = smem;                 // [3][4096]
    uint32_t* sBm = smem + 12288;         // [3][4096]
    const uint32_t sAu = smem_u32(sAm);
    const uint32_t sBu = smem_u32(sBm);

    const int t = threadIdx.x;
    const int KS = K >> 3;
    const int m0 = blockIdx.y * 128;
    const int n0 = blockIdx.x * 128;
    const int w = t >> 5, lane = t & 31;
    const int wy = w >> 2, wx = w & 3;
    const int gid = lane >> 2, tig = lane & 3;

    const uint32_t* Abase = g_Ap + (size_t)(blockIdx.y * 8) * KS * 128;
    const uint32_t* Bbase = g_Bp + (size_t)(blockIdx.x * 16) * KS * 64;

    float acc[4][4][4];
#pragma unroll
    for (int mi = 0; mi < 4; mi++)
#pragma unroll
        for (int ni = 0; ni < 4; ni++)
#pragma unroll
            for (int j = 0; j < 4; j++) acc[mi][ni][j] = 0.f;

    const int nc = K / 32;

    auto load_chunk = [&](int c, int s) {
        uint32_t ab = sAu + (uint32_t)s * 16384u;
        uint32_t bb = sBu + (uint32_t)s * 16384u;
#pragma unroll
        for (int q = 0; q < 4; q++) {
            int i4 = t + q * 256;
            int mt = i4 >> 7, rema = (i4 & 127) << 2;
            cp16(ab + (uint32_t)i4 * 16,
                 Abase + (size_t)mt * KS * 128 + c * 512 + rema);
            int nt = i4 >> 6, remb = (i4 & 63) << 2;
            cp16(bb + (uint32_t)i4 * 16,
                 Bbase + (size_t)nt * KS * 64 + c * 256 + remb);
        }
    };

    load_chunk(0, 0);
    asm volatile("cp.async.commit_group;" ::: "memory");
    load_chunk(1, 1);
    asm volatile("cp.async.commit_group;" ::: "memory");

    for (int c = 0; c < nc; ++c) {
        int s = c - (c / 3) * 3;
        asm volatile("cp.async.wait_group 1;" ::: "memory");
        __syncthreads();
        if (c + 2 < nc) {
            int s2 = (c + 2) - ((c + 2) / 3) * 3;
            load_chunk(c + 2, s2);
            asm volatile("cp.async.commit_group;" ::: "memory");
        } else {
            asm volatile("cp.async.commit_group;" ::: "memory");
        }

        const uint32_t* As = sAm + s * 4096;
        const uint32_t* Bs = sBm + s * 4096;
#pragma unroll
        for (int ksp = 0; ksp < 4; ksp++) {
            uint4 af[4];
            uint2 bf[4];
#pragma unroll
            for (int mi = 0; mi < 4; mi++)
                af[mi] = *(const uint4*)&As[(((wy * 4 + mi) * 4 + ksp) << 7) + (lane << 2)];
#pragma unroll
            for (int ni = 0; ni < 4; ni++)
                bf[ni] = *(const uint2*)&Bs[(((wx * 4 + ni) * 4 + ksp) << 6) + (lane << 1)];
#pragma unroll
            for (int mi = 0; mi < 4; mi++)
#pragma unroll
                for (int ni = 0; ni < 4; ni++)
                    MMA_TF32(acc[mi][ni], af[mi].x, af[mi].y, af[mi].z, af[mi].w,
                             bf[ni].x, bf[ni].y);
        }
    }

#pragma unroll
    for (int mi = 0; mi < 4; mi++) {
        int r0 = m0 + wy * 64 + mi * 16 + gid;
#pragma unroll
        for (int ni = 0; ni < 4; ni++) {
            int feat = n0 + wx * 32 + ni * 8 + 2 * tig;
            float2 bb = *(const float2*)&bias[feat];
            if (MODE == 0) {
                int sec = feat >> 10, hm = feat & 1023;
                float* p = (sec == 0) ? g_q : ((sec == 1) ? g_k : g_v);
                float sc = (sec == 1) ? 0.125f : 1.0f;
                int h = hm >> 6, d = hm & 63;
                float2 v0 = make_float2((acc[mi][ni][0] + bb.x) * sc,
                                        (acc[mi][ni][1] + bb.y) * sc);
                float2 v1 = make_float2((acc[mi][ni][2] + bb.x) * sc,
                                        (acc[mi][ni][3] + bb.y) * sc);
                *(float2*)&p[((h * Nn + r0) << 6) + d] = v0;
                *(float2*)&p[((h * Nn + r0 + 8) << 6) + d] = v1;
            } else {
                float2 v0 = make_float2(acc[mi][ni][0] + bb.x, acc[mi][ni][1] + bb.y);
                float2 v1 = make_float2(acc[mi][ni][2] + bb.x, acc[mi][ni][3] + bb.y);
                *(float2*)&out[(size_t)r0 * Dd + feat] = v0;
                *(float2*)&out[(size_t)(r0 + 8) * Dd + feat] = v1;
            }
        }
    }
}

// ---------------- fused banded attention + pos logits, 64q/512t ----------
#define QT 64
#define BND 288
#define ERWS 224
#define BP 68
#define SSP 516
#define SQ_F (QT * BP)
#define SB_F (BND * BP)
#define SS_F (QT * SSP)
#define ATTN_SMEM_BYTES ((SQ_F + SB_F + SS_F) * 4)   // 227840

__global__ void __launch_bounds__(512) attn_kernel(const float* __restrict__ rel_emb)
{
    extern __shared__ __align__(16) float sm[];
    float* sQ = sm;                    // [64][BP]  (tf32 bits)
    float* sB = sm + SQ_F;             // [288][BP] (tf32 bits): E -> K -> V
    float* sS = sm + SQ_F + SB_F;      // [64][SSP]: 0..287 Sqk->P, 288..511 Spos

    const int h = blockIdx.y;
    const int i0 = blockIdx.x * QT;
    const int jlo = i0 - RAD;
    const int t = threadIdx.x;
    const int w = t >> 5, lane = t & 31;
    const int gid = lane >> 2, tig = lane & 3;
    const int mw = w & 3, nw = w >> 2;    // 4 m-groups x 4 n-groups

    // ---- load Q (64x64, tf32) and E (224 rows, tf32, zero-padded) ----
    for (int idx = t; idx < QT * 16; idx += 512) {
        int qi = idx >> 4, d4 = (idx & 15) << 2;
        float4 v = *(const float4*)&g_q[((h * Nn + i0 + qi) << 6) + d4];
        *(float4*)&sQ[qi * BP + d4] = make_float4(f2tff(v.x), f2tff(v.y),
                                                  f2tff(v.z), f2tff(v.w));
    }
    const float* E = rel_emb + (size_t)h * NEMB * HD;
    for (int idx = t; idx < ERWS * 16; idx += 512) {
        int r = idx >> 4, d4 = (idx & 15) << 2;
        float4 o = make_float4(0.f, 0.f, 0.f, 0.f);
        if (r < NEMB) {
            float4 v = *(const float4*)&E[r * HD + d4];
            o = make_float4(f2tff(v.x), f2tff(v.y), f2tff(v.z), f2tff(v.w));
        }
        *(float4*)&sB[r * BP + d4] = o;
    }
    __syncthreads();

    // ---- Spos = Q @ E^T (64x224) ----
    {
        float acc[7][4];
#pragma unroll
        for (int f = 0; f < 7; f++)
#pragma unroll
            for (int j = 0; j < 4; j++) acc[f][j] = 0.f;
#pragma unroll
        for (int ks = 0; ks < 8; ks++) {
            int kb = ks * 8 + tig;
            uint32_t a0 = __float_as_uint(sQ[(mw * 16 + gid) * BP + kb]);
            uint32_t a1 = __float_as_uint(sQ[(mw * 16 + gid + 8) * BP + kb]);
            uint32_t a2 = __float_as_uint(sQ[(mw * 16 + gid) * BP + kb + 4]);
            uint32_t a3 = __float_as_uint(sQ[(mw * 16 + gid + 8) * BP + kb + 4]);
#pragma unroll
            for (int f = 0; f < 7; f++) {
                int nb = (nw * 7 + f) * 8;
                uint32_t b0 = __float_as_uint(sB[(nb + gid) * BP + kb]);
                uint32_t b1 = __float_as_uint(sB[(nb + gid) * BP + kb + 4]);
                MMA_TF32(acc[f], a0, a1, a2, a3, b0, b1);
            }
        }
        int r0 = mw * 16 + gid;
#pragma unroll
        for (int f = 0; f < 7; f++) {
            int col = BND + (nw * 7 + f) * 8 + 2 * tig;
            *(float2*)&sS[r0 * SSP + col] = make_float2(acc[f][0], acc[f][1]);
            *(float2*)&sS[(r0 + 8) * SSP + col] = make_float2(acc[f][2], acc[f][3]);
        }
    }
    __syncthreads();

    // ---- overwrite sB with K band (tf32, zero OOB) ----
    for (int idx = t; idx < BND * 16; idx += 512) {
        int jj = idx >> 4, d4 = (idx & 15) << 2;
        int j = jlo + jj;
        float4 o = make_float4(0.f, 0.f, 0.f, 0.f);
        if (j >= 0 && j < Nn) {
            float4 v = *(const float4*)&g_k[((h * Nn + j) << 6) + d4];
            o = make_float4(f2tff(v.x), f2tff(v.y), f2tff(v.z), f2tff(v.w));
        }
        *(float4*)&sB[jj * BP + d4] = o;
    }
    __syncthreads();

    // ---- Sqk (band-restricted): warp (mw,nw) -> frags 2mw + nw*7 .. +6 ----
    // m-tile mw needs cols [16mw, 16mw+214) => 28 frags starting at 2mw.
    {
        float acc[7][4];
#pragma unroll
        for (int f = 0; f < 7; f++)
#pragma unroll
            for (int j = 0; j < 4; j++) acc[f][j] = 0.f;
#pragma unroll
        for (int ks = 0; ks < 8; ks++) {
            int kb = ks * 8 + tig;
            uint32_t a0 = __float_as_uint(sQ[(mw * 16 + gid) * BP + kb]);
            uint32_t a1 = __float_as_uint(sQ[(mw * 16 + gid + 8) * BP + kb]);
            uint32_t a2 = __float_as_uint(sQ[(mw * 16 + gid) * BP + kb + 4]);
            uint32_t a3 = __float_as_uint(sQ[(mw * 16 + gid + 8) * BP + kb + 4]);
#pragma unroll
            for (int f = 0; f < 7; f++) {
                int nb = (2 * mw + nw * 7 + f) * 8;
                uint32_t b0 = __float_as_uint(sB[(nb + gid) * BP + kb]);
                uint32_t b1 = __float_as_uint(sB[(nb + gid) * BP + kb + 4]);
                MMA_TF32(acc[f], a0, a1, a2, a3, b0, b1);
            }
        }
        int r0 = mw * 16 + gid;
#pragma unroll
        for (int f = 0; f < 7; f++) {
            int col = (2 * mw + nw * 7 + f) * 8 + 2 * tig;
            *(float2*)&sS[r0 * SSP + col] = make_float2(acc[f][0], acc[f][1]);
            *(float2*)&sS[(r0 + 8) * SSP + col] = make_float2(acc[f][2], acc[f][3]);
        }
    }
    __syncthreads();

    // ---- overwrite sB with V band (tf32); softmax on independent region ----
    for (int idx = t; idx < BND * 16; idx += 512) {
        int jj = idx >> 4, d4 = (idx & 15) << 2;
        int j = jlo + jj;
        float4 o = make_float4(0.f, 0.f, 0.f, 0.f);
        if (j >= 0 && j < Nn) {
            float4 v = *(const float4*)&g_v[((h * Nn + j) << 6) + d4];
            o = make_float4(f2tff(v.x), f2tff(v.y), f2tff(v.z), f2tff(v.w));
        }
        *(float4*)&sB[jj * BP + d4] = o;
    }

    // ---- banded softmax, 4 rows per warp in ILP (rows w*4..w*4+3) ----
    {
        const int Q0 = (w >> 2) * 16;       // m-tile base of this warp's rows
        float v[4][7];
#pragma unroll
        for (int p = 0; p < 4; p++) {
            int qi = w * 4 + p;
            int i = i0 + qi;
#pragma unroll
            for (int u = 0; u < 7; u++) {
                int r = lane + u * 32;
                float val = -1e30f;
                if (r < NEMB) {
                    int j = i - RAD + r;
                    if (j >= 0 && j < Nn)
                        val = sS[qi * SSP + qi + r] + sS[qi * SSP + BND + r];
                }
                v[p][u] = val;
            }
        }
        float mx[4];
#pragma unroll
        for (int p = 0; p < 4; p++) {
            mx[p] = v[p][0];
#pragma unroll
            for (int u = 1; u < 7; u++) mx[p] = fmaxf(mx[p], v[p][u]);
        }
#pragma unroll
        for (int off = 16; off; off >>= 1)
#pragma unroll
            for (int p = 0; p < 4; p++)
                mx[p] = fmaxf(mx[p], __shfl_xor_sync(0xffffffffu, mx[p], off));
        float s[4] = {0.f, 0.f, 0.f, 0.f};
#pragma unroll
        for (int p = 0; p < 4; p++)
#pragma unroll
            for (int u = 0; u < 7; u++) {
                v[p][u] = (v[p][u] > -1e29f) ? __expf(v[p][u] - mx[p]) : 0.f;
                s[p] += v[p][u];
            }
#pragma unroll
        for (int off = 16; off; off >>= 1)
#pragma unroll
            for (int p = 0; p < 4; p++)
                s[p] += __shfl_xor_sync(0xffffffffu, s[p], off);
        float inv[4];
#pragma unroll
        for (int p = 0; p < 4; p++) inv[p] = 1.f / s[p];

        // zero only the m-tile window [Q0, Q0+224)
#pragma unroll
        for (int p = 0; p < 4; p++) {
            int qi = w * 4 + p;
#pragma unroll
            for (int u = 0; u < 7; u++)
                sS[qi * SSP + Q0 + lane + u * 32] = 0.f;
        }
        __syncwarp();
#pragma unroll
        for (int p = 0; p < 4; p++) {
            int qi = w * 4 + p;
#pragma unroll
            for (int u = 0; u < 7; u++) {
                int r = lane + u * 32;
                if (r < NEMB && v[p][u] != 0.f)
                    sS[qi * SSP + qi + r] = f2tff(v[p][u] * inv[p]);
            }
        }
    }
    __syncthreads();

    // ---- O = P @ V, band-restricted: m-tile mw uses ks 2mw .. 2mw+26 ----
    {
        float acc[2][4];
#pragma unroll
        for (int ff = 0; ff < 2; ff++)
#pragma unroll
            for (int j = 0; j < 4; j++) acc[ff][j] = 0.f;

        const int kbase = mw * 16;
#pragma unroll
        for (int ks = 0; ks < 27; ks++) {
            int kb = kbase + ks * 8 + tig;
            uint32_t a0 = __float_as_uint(sS[(mw * 16 + gid) * SSP + kb]);
            uint32_t a1 = __float_as_uint(sS[(mw * 16 + gid + 8) * SSP + kb]);
            uint32_t a2 = __float_as_uint(sS[(mw * 16 + gid) * SSP + kb + 4]);
            uint32_t a3 = __float_as_uint(sS[(mw * 16 + gid + 8) * SSP + kb + 4]);
#pragma unroll
            for (int ff = 0; ff < 2; ff++) {
                int nd = (nw * 2 + ff) * 8 + gid;
                uint32_t b0 = __float_as_uint(sB[kb * BP + nd]);
                uint32_t b1 = __float_as_uint(sB[(kb + 4) * BP + nd]);
                MMA_TF32(acc[ff], a0, a1, a2, a3, b0, b1);
            }
        }
        int row = mw * 16 + gid;
#pragma unroll
        for (int ff = 0; ff < 2; ff++) {
            int dcol = h * 64 + (nw * 2 + ff) * 8 + 2 * tig;
            *(float2*)&g_ao[(size_t)(i0 + row) * Dd + dcol] =
                make_float2(acc[ff][0], acc[ff][1]);
            *(float2*)&g_ao[(size_t)(i0 + row + 8) * Dd + dcol] =
                make_float2(acc[ff][2], acc[ff][3]);
        }
    }
}

// ---------------- launcher ------------------------------------------------
extern "C" void kernel_launch(void* const* d_in, const int* in_sizes, int n_in,
                              void* d_out, int out_size)
{
    (void)in_sizes; (void)n_in; (void)out_size;
    const float* x      = (const float*)d_in[0];
    const float* qkv_w  = (const float*)d_in[1];
    const float* qkv_b  = (const float*)d_in[2];
    const float* proj_w = (const float*)d_in[3];
    const float* proj_b = (const float*)d_in[4];
    const float* rel    = (const float*)d_in[5];
    float* out = (float*)d_out;

    cudaFuncSetAttribute(mma_gemm<0>, cudaFuncAttributeMaxDynamicSharedMemorySize,
                         GEMM_SMEM_BYTES);
    cudaFuncSetAttribute(mma_gemm<1>, cudaFuncAttributeMaxDynamicSharedMemorySize,
                         GEMM_SMEM_BYTES);
    cudaFuncSetAttribute(attn_kernel, cudaFuncAttributeMaxDynamicSharedMemorySize,
                         ATTN_SMEM_BYTES);

    // 1) pack x (A-frags) and qkv_w (B-frags)
    packA<0><<<(Nn / 16) * (Dd / 8) * 32 / 256, 256>>>(x, Nn, Dd);
    packB<<<(3 * Dd / 8) * (Dd / 8) * 32 / 256, 256>>>(qkv_w, 3 * Dd, Dd);
    // 2) QKV GEMM: scatter q / k(scaled) / v
    mma_gemm<0><<<dim3(3 * Dd / 128, Nn / 128), 256, GEMM_SMEM_BYTES>>>(qkv_b,
                                                                        nullptr, Dd);
    // 3) fused pos + banded attention (64q/512t) -> g_ao
    attn_kernel<<<dim3(Nn / QT, Hh), 512, ATTN_SMEM_BYTES>>>(rel);
    // 4) pack g_ao (A-frags) and proj_w (B-frags)
    packA<1><<<(Nn / 16) * (Dd / 8) * 32 / 256, 256>>>(nullptr, Nn, Dd);
    packB<<<(Dd / 8) * (Dd / 8) * 32 / 256, 256>>>(proj_w, Dd, Dd);
    // 5) output projection -> d_out
    mma_gemm<1><<<dim3(Dd / 128, Nn / 128), 256, GEMM_SMEM_BYTES>>>(proj_b, out, Dd);
}

// round 10
// speedup vs baseline: 1.3588x; 1.0944x over previous
#include <cuda_runtime.h>
#include <cstdint>

#define Nn 2048
#define Dd 1024
#define Hh 16
#define HD 64
#define NEMB 199
#define RAD 99

// ---------------- scratch (device globals; no allocation) ----------------
__device__ float g_q[Hh * Nn * HD];        // tf32 bits
__device__ float g_k[Hh * Nn * HD];        // tf32 bits, pre-scaled by 1/8
__device__ float g_v[Hh * Nn * HD];        // tf32 bits
__device__ float g_Et[Hh * 224 * HD];      // tf32 rel_emb, zero-padded to 224 rows
__device__ float g_ao[Nn * Dd];
__device__ uint32_t g_Ap[Nn * Dd];         // packed A frags (tf32 bits)
__device__ uint32_t g_Bp[3 * Dd * Dd];     // packed B frags (tf32 bits)

// ---------------- common helpers ------------------------------------------
__device__ __forceinline__ uint32_t f2tf(float f) {
    uint32_t u;
    asm("cvt.rna.tf32.f32 %0, %1;" : "=r"(u) : "f"(f));
    return u;
}
__device__ __forceinline__ float f2tff(float f) {
    return __uint_as_float(f2tf(f));
}
__device__ __forceinline__ uint32_t smem_u32(const void* p) {
    uint32_t a;
    asm("{ .reg .u64 t; cvta.to.shared.u64 t, %1; cvt.u32.u64 %0, t; }"
        : "=r"(a) : "l"(p));
    return a;
}
__device__ __forceinline__ void cp16(uint32_t dst, const void* src) {
    asm volatile("cp.async.cg.shared.global [%0], [%1], 16;" :: "r"(dst), "l"(src) : "memory");
}

#define MMA_TF32(d, a0, a1, a2, a3, b0, b1) \
    asm volatile( \
        "mma.sync.aligned.m16n8k8.row.col.f32.tf32.tf32.f32 " \
        "{%0,%1,%2,%3}, {%4,%5,%6,%7}, {%8,%9}, {%0,%1,%2,%3};" \
        : "+f"((d)[0]), "+f"((d)[1]), "+f"((d)[2]), "+f"((d)[3]) \
        : "r"(a0), "r"(a1), "r"(a2), "r"(a3), "r"(b0), "r"(b1))

// ---------------- pack kernels: fp32 -> fragment-ready tf32 ----------------
template <int SRCAO>
__global__ void __launch_bounds__(256) packA(const float* __restrict__ src,
                                             int rows, int K)
{
    const float* in = SRCAO ? (const float*)g_ao : src;
    int idx = blockIdx.x * 256 + threadIdx.x;
    int KS = K >> 3;
    int total = (rows >> 4) * KS * 32;
    if (idx >= total) return;
    int lane = idx & 31;
    int ks = (idx >> 5) % KS;
    int mt = (idx >> 5) / KS;
    int gid = lane >> 2, tig = lane & 3;
    int r0 = mt * 16 + gid, c0 = ks * 8 + tig;
    uint4 o;
    o.x = f2tf(in[(size_t)r0 * K + c0]);
    o.y = f2tf(in[(size_t)(r0 + 8) * K + c0]);
    o.z = f2tf(in[(size_t)r0 * K + c0 + 4]);
    o.w = f2tf(in[(size_t)(r0 + 8) * K + c0 + 4]);
    *(uint4*)&g_Ap[(size_t)idx * 4] = o;
}

__global__ void __launch_bounds__(256) packB(const float* __restrict__ src,
                                             int rowsB, int K)
{
    int idx = blockIdx.x * 256 + threadIdx.x;
    int KS = K >> 3;
    int total = (rowsB >> 3) * KS * 32;
    if (idx >= total) return;
    int lane = idx & 31;
    int ks = (idx >> 5) % KS;
    int nt = (idx >> 5) / KS;
    int gid = lane >> 2, tig = lane & 3;
    int n = nt * 8 + gid, c0 = ks * 8 + tig;
    uint2 o;
    o.x = f2tf(src[(size_t)n * K + c0]);
    o.y = f2tf(src[(size_t)n * K + c0 + 4]);
    *(uint2*)&g_Bp[(size_t)idx * 2] = o;
}

// tf32 rel_emb, zero-padded rows [NEMB, 224)
__global__ void __launch_bounds__(256) packE(const float* __restrict__ rel)
{
    int idx = blockIdx.x * 256 + threadIdx.x;
    if (idx >= Hh * 224 * HD) return;
    int d = idx & 63;
    int r = (idx >> 6) % 224;
    int h = idx / (224 * 64);
    float v = 0.f;
    if (r < NEMB) v = f2tff(rel[((size_t)h * NEMB + r) * HD + d]);
    g_Et[idx] = v;
}

// ---------------- tf32 mma.sync GEMM, 3-stage cp.async --------------------
#define GEMM_SMEM_BYTES 98304

template <int MODE>
__global__ void __launch_bounds__(256) mma_gemm(
    const float* __restrict__ bias, float* __restrict__ out, int K)
{
    extern __shared__ __align__(16) uint32_t smem[];
    uint32_t* sAm = smem;
    uint32_t* sBm = smem + 12288;
    const uint32_t sAu = smem_u32(sAm);
    const uint32_t sBu = smem_u32(sBm);

    const int t = threadIdx.x;
    const int KS = K >> 3;
    const int m0 = blockIdx.y * 128;
    const int n0 = blockIdx.x * 128;
    const int w = t >> 5, lane = t & 31;
    const int wy = w >> 2, wx = w & 3;
    const int gid = lane >> 2, tig = lane & 3;

    const uint32_t* Abase = g_Ap + (size_t)(blockIdx.y * 8) * KS * 128;
    const uint32_t* Bbase = g_Bp + (size_t)(blockIdx.x * 16) * KS * 64;

    float acc[4][4][4];
#pragma unroll
    for (int mi = 0; mi < 4; mi++)
#pragma unroll
        for (int ni = 0; ni < 4; ni++)
#pragma unroll
            for (int j = 0; j < 4; j++) acc[mi][ni][j] = 0.f;

    const int nc = K / 32;

    auto load_chunk = [&](int c, int s) {
        uint32_t ab = sAu + (uint32_t)s * 16384u;
        uint32_t bb = sBu + (uint32_t)s * 16384u;
#pragma unroll
        for (int q = 0; q < 4; q++) {
            int i4 = t + q * 256;
            int mt = i4 >> 7, rema = (i4 & 127) << 2;
            cp16(ab + (uint32_t)i4 * 16,
                 Abase + (size_t)mt * KS * 128 + c * 512 + rema);
            int nt = i4 >> 6, remb = (i4 & 63) << 2;
            cp16(bb + (uint32_t)i4 * 16,
                 Bbase + (size_t)nt * KS * 64 + c * 256 + remb);
        }
    };

    load_chunk(0, 0);
    asm volatile("cp.async.commit_group;" ::: "memory");
    load_chunk(1, 1);
    asm volatile("cp.async.commit_group;" ::: "memory");

    for (int c = 0; c < nc; ++c) {
        int s = c - (c / 3) * 3;
        asm volatile("cp.async.wait_group 1;" ::: "memory");
        __syncthreads();
        if (c + 2 < nc) {
            int s2 = (c + 2) - ((c + 2) / 3) * 3;
            load_chunk(c + 2, s2);
            asm volatile("cp.async.commit_group;" ::: "memory");
        } else {
            asm volatile("cp.async.commit_group;" ::: "memory");
        }

        const uint32_t* As = sAm + s * 4096;
        const uint32_t* Bs = sBm + s * 4096;
#pragma unroll
        for (int ksp = 0; ksp < 4; ksp++) {
            uint4 af[4];
            uint2 bf[4];
#pragma unroll
            for (int mi = 0; mi < 4; mi++)
                af[mi] = *(const uint4*)&As[(((wy * 4 + mi) * 4 + ksp) << 7) + (lane << 2)];
#pragma unroll
            for (int ni = 0; ni < 4; ni++)
                bf[ni] = *(const uint2*)&Bs[(((wx * 4 + ni) * 4 + ksp) << 6) + (lane << 1)];
#pragma unroll
            for (int mi = 0; mi < 4; mi++)
#pragma unroll
                for (int ni = 0; ni < 4; ni++)
                    MMA_TF32(acc[mi][ni], af[mi].x, af[mi].y, af[mi].z, af[mi].w,
                             bf[ni].x, bf[ni].y);
        }
    }

#pragma unroll
    for (int mi = 0; mi < 4; mi++) {
        int r0 = m0 + wy * 64 + mi * 16 + gid;
#pragma unroll
        for (int ni = 0; ni < 4; ni++) {
            int feat = n0 + wx * 32 + ni * 8 + 2 * tig;
            float2 bb = *(const float2*)&bias[feat];
            if (MODE == 0) {
                int sec = feat >> 10, hm = feat & 1023;
                float* p = (sec == 0) ? g_q : ((sec == 1) ? g_k : g_v);
                float sc = (sec == 1) ? 0.125f : 1.0f;
                int h = hm >> 6, d = hm & 63;
                // store tf32-rounded (consumed only by attn MMAs)
                float2 v0 = make_float2(f2tff((acc[mi][ni][0] + bb.x) * sc),
                                        f2tff((acc[mi][ni][1] + bb.y) * sc));
                float2 v1 = make_float2(f2tff((acc[mi][ni][2] + bb.x) * sc),
                                        f2tff((acc[mi][ni][3] + bb.y) * sc));
                *(float2*)&p[((h * Nn + r0) << 6) + d] = v0;
                *(float2*)&p[((h * Nn + r0 + 8) << 6) + d] = v1;
            } else {
                float2 v0 = make_float2(acc[mi][ni][0] + bb.x, acc[mi][ni][1] + bb.y);
                float2 v1 = make_float2(acc[mi][ni][2] + bb.x, acc[mi][ni][3] + bb.y);
                *(float2*)&out[(size_t)r0 * Dd + feat] = v0;
                *(float2*)&out[(size_t)(r0 + 8) * Dd + feat] = v1;
            }
        }
    }
}

// ---------------- fused banded attention + pos logits, 64q/512t ----------
// cp.async everywhere; Spos held in regs, merged into band-relative S.
#define QT 64
#define BND 288
#define ERWS 224
#define BP 68
#define SSP2 244           // band-relative S pitch
#define SQ_F (QT * BP)                 // 4352
#define SE_F (ERWS * BP)               // 15232
#define SB_F (BND * BP)                // 19584
#define SS_F (QT * SSP2)               // 15616
#define ATTN_SMEM_BYTES ((SQ_F + SE_F + SB_F + SS_F) * 4)   // 219136

__global__ void __launch_bounds__(512) attn_kernel()
{
    extern __shared__ __align__(16) float sm[];
    float* sQ = sm;                    // [64][BP]
    float* sE = sm + SQ_F;             // [224][BP]
    float* sB = sm + SQ_F + SE_F;      // [288][BP]: K -> V
    float* sS = sm + SQ_F + SE_F + SB_F; // [64][SSP2] band-relative S/P
    const uint32_t sQu = smem_u32(sQ);
    const uint32_t sEu = smem_u32(sE);
    const uint32_t sBu = smem_u32(sB);

    const int h = blockIdx.y;
    const int i0 = blockIdx.x * QT;
    const int jlo = i0 - RAD;
    const int t = threadIdx.x;
    const int w = t >> 5, lane = t & 31;
    const int gid = lane >> 2, tig = lane & 3;
    const int mw = w & 3, nw = w >> 2;

    // ---- issue Q + E cp.async (group A) ----
    const float* Qg = g_q + ((size_t)(h * Nn + i0) << 6);
    for (int idx = t; idx < QT * 16; idx += 512) {
        int qi = idx >> 4, d4 = (idx & 15) << 2;
        cp16(sQu + (uint32_t)(qi * BP + d4) * 4, Qg + (qi << 6) + d4);
    }
    const float* Eg = g_Et + (size_t)h * ERWS * HD;
    for (int idx = t; idx < ERWS * 16; idx += 512) {
        int r = idx >> 4, d4 = (idx & 15) << 2;
        cp16(sEu + (uint32_t)(r * BP + d4) * 4, Eg + r * HD + d4);
    }
    asm volatile("cp.async.commit_group;" ::: "memory");

    // ---- issue K band cp.async (group B), zero-fill invalid rows ----
    for (int idx = t; idx < BND * 16; idx += 512) {
        int jj = idx >> 4, d4 = (idx & 15) << 2;
        int j = jlo + jj;
        if (j >= 0 && j < Nn)
            cp16(sBu + (uint32_t)(jj * BP + d4) * 4,
                 g_k + (((size_t)(h * Nn) + j) << 6) + d4);
        else
            *(float4*)&sB[jj * BP + d4] = make_float4(0.f, 0.f, 0.f, 0.f);
    }
    asm volatile("cp.async.commit_group;" ::: "memory");

    asm volatile("cp.async.wait_group 1;" ::: "memory");
    __syncthreads();

    // ---- Spos = Q @ E^T, accumulators kept in registers ----
    float pacc[7][4];
#pragma unroll
    for (int f = 0; f < 7; f++)
#pragma unroll
        for (int j = 0; j < 4; j++) pacc[f][j] = 0.f;
#pragma unroll
    for (int ks = 0; ks < 8; ks++) {
        int kb = ks * 8 + tig;
        uint32_t a0 = __float_as_uint(sQ[(mw * 16 + gid) * BP + kb]);
        uint32_t a1 = __float_as_uint(sQ[(mw * 16 + gid + 8) * BP + kb]);
        uint32_t a2 = __float_as_uint(sQ[(mw * 16 + gid) * BP + kb + 4]);
        uint32_t a3 = __float_as_uint(sQ[(mw * 16 + gid + 8) * BP + kb + 4]);
#pragma unroll
        for (int f = 0; f < 7; f++) {
            int nb = (nw * 7 + f) * 8;
            uint32_t b0 = __float_as_uint(sE[(nb + gid) * BP + kb]);
            uint32_t b1 = __float_as_uint(sE[(nb + gid) * BP + kb + 4]);
            MMA_TF32(pacc[f], a0, a1, a2, a3, b0, b1);
        }
    }

    asm volatile("cp.async.wait_group 0;" ::: "memory");
    __syncthreads();

    // ---- Sqk band-restricted -> store band-relative: local col = jj - 16mw --
    {
        float acc[7][4];
#pragma unroll
        for (int f = 0; f < 7; f++)
#pragma unroll
            for (int j = 0; j < 4; j++) acc[f][j] = 0.f;
#pragma unroll
        for (int ks = 0; ks < 8; ks++) {
            int kb = ks * 8 + tig;
            uint32_t a0 = __float_as_uint(sQ[(mw * 16 + gid) * BP + kb]);
            uint32_t a1 = __float_as_uint(sQ[(mw * 16 + gid + 8) * BP + kb]);
            uint32_t a2 = __float_as_uint(sQ[(mw * 16 + gid) * BP + kb + 4]);
            uint32_t a3 = __float_as_uint(sQ[(mw * 16 + gid + 8) * BP + kb + 4]);
#pragma unroll
            for (int f = 0; f < 7; f++) {
                int nb = (2 * mw + nw * 7 + f) * 8;
                uint32_t b0 = __float_as_uint(sB[(nb + gid) * BP + kb]);
                uint32_t b1 = __float_as_uint(sB[(nb + gid) * BP + kb + 4]);
                MMA_TF32(acc[f], a0, a1, a2, a3, b0, b1);
            }
        }
        int r0 = mw * 16 + gid;
#pragma unroll
        for (int f = 0; f < 7; f++) {
            int col = (nw * 7 + f) * 8 + 2 * tig;   // local = global - 16mw
            *(float2*)&sS[r0 * SSP2 + col] = make_float2(acc[f][0], acc[f][1]);
            *(float2*)&sS[(r0 + 8) * SSP2 + col] = make_float2(acc[f][2], acc[f][3]);
        }
    }
    __syncthreads();

    // ---- issue V band cp.async (overwrites sB) ----
    for (int idx = t; idx < BND * 16; idx += 512) {
        int jj = idx >> 4, d4 = (idx & 15) << 2;
        int j = jlo + jj;
        if (j >= 0 && j < Nn)
            cp16(sBu + (uint32_t)(jj * BP + d4) * 4,
                 g_v + (((size_t)(h * Nn) + j) << 6) + d4);
        else
            *(float4*)&sB[jj * BP + d4] = make_float4(0.f, 0.f, 0.f, 0.f);
    }
    asm volatile("cp.async.commit_group;" ::: "memory");

    // ---- merge pos into S (scalar: diagonal shift makes offsets odd) ----
    {
        int rl0 = gid, rl1 = gid + 8;          // local rows within m-tile mw
        int q0 = mw * 16 + gid, q1 = q0 + 8;   // tile rows
#pragma unroll
        for (int f = 0; f < 7; f++) {
            int r = (nw * 7 + f) * 8 + 2 * tig;
            float* p0 = &sS[q0 * SSP2 + rl0 + r];
            p0[0] += pacc[f][0];
            p0[1] += pacc[f][1];
            float* p1 = &sS[q1 * SSP2 + rl1 + r];
            p1[0] += pacc[f][2];
            p1[1] += pacc[f][3];
        }
    }
    __syncthreads();

    // ---- banded softmax, 4 rows/warp ILP; P written as tf32 ----
    {
        float v[4][7];
#pragma unroll
        for (int p = 0; p < 4; p++) {
            int qi = w * 4 + p;
            int ql = qi & 15;
            int i = i0 + qi;
#pragma unroll
            for (int u = 0; u < 7; u++) {
                int r = lane + u * 32;
                float val = -1e30f;
                if (r < NEMB) {
                    int j = i - RAD + r;
                    if (j >= 0 && j < Nn)
                        val = sS[qi * SSP2 + ql + r];
                }
                v[p][u] = val;
            }
        }
        float mx[4];
#pragma unroll
        for (int p = 0; p < 4; p++) {
            mx[p] = v[p][0];
#pragma unroll
            for (int u = 1; u < 7; u++) mx[p] = fmaxf(mx[p], v[p][u]);
        }
#pragma unroll
        for (int off = 16; off; off >>= 1)
#pragma unroll
            for (int p = 0; p < 4; p++)
                mx[p] = fmaxf(mx[p], __shfl_xor_sync(0xffffffffu, mx[p], off));
        float s[4] = {0.f, 0.f, 0.f, 0.f};
#pragma unroll
        for (int p = 0; p < 4; p++)
#pragma unroll
            for (int u = 0; u < 7; u++) {
                v[p][u] = (v[p][u] > -1e29f) ? __expf(v[p][u] - mx[p]) : 0.f;
                s[p] += v[p][u];
            }
#pragma unroll
        for (int off = 16; off; off >>= 1)
#pragma unroll
            for (int p = 0; p < 4; p++)
                s[p] += __shfl_xor_sync(0xffffffffu, s[p], off);
        float inv[4];
#pragma unroll
        for (int p = 0; p < 4; p++) inv[p] = 1.f / s[p];

        // zero cols [0,224), then write normalized P at band positions
#pragma unroll
        for (int p = 0; p < 4; p++) {
            int qi = w * 4 + p;
#pragma unroll
            for (int u = 0; u < 7; u++)
                sS[qi * SSP2 + lane + u * 32] = 0.f;
        }
        __syncwarp();
#pragma unroll
        for (int p = 0; p < 4; p++) {
            int qi = w * 4 + p;
            int ql = qi & 15;
#pragma unroll
            for (int u = 0; u < 7; u++) {
                int r = lane + u * 32;
                if (r < NEMB && v[p][u] != 0.f)
                    sS[qi * SSP2 + ql + r] = f2tff(v[p][u] * inv[p]);
            }
        }
    }
    asm volatile("cp.async.wait_group 0;" ::: "memory");
    __syncthreads();

    // ---- O = P @ V (band-relative): A cols [0,216), B rows 16mw + kb ----
    {
        float acc[2][4];
#pragma unroll
        for (int ff = 0; ff < 2; ff++)
#pragma unroll
            for (int j = 0; j < 4; j++) acc[ff][j] = 0.f;

#pragma unroll
        for (int ks = 0; ks < 27; ks++) {
            int kb = ks * 8 + tig;
            uint32_t a0 = __float_as_uint(sS[(mw * 16 + gid) * SSP2 + kb]);
            uint32_t a1 = __float_as_uint(sS[(mw * 16 + gid + 8) * SSP2 + kb]);
            uint32_t a2 = __float_as_uint(sS[(mw * 16 + gid) * SSP2 + kb + 4]);
            uint32_t a3 = __float_as_uint(sS[(mw * 16 + gid + 8) * SSP2 + kb + 4]);
            int vrow = mw * 16 + kb;
#pragma unroll
            for (int ff = 0; ff < 2; ff++) {
                int nd = (nw * 2 + ff) * 8 + gid;
                uint32_t b0 = __float_as_uint(sB[vrow * BP + nd]);
                uint32_t b1 = __float_as_uint(sB[(vrow + 4) * BP + nd]);
                MMA_TF32(acc[ff], a0, a1, a2, a3, b0, b1);
            }
        }
        int row = mw * 16 + gid;
#pragma unroll
        for (int ff = 0; ff < 2; ff++) {
            int dcol = h * 64 + (nw * 2 + ff) * 8 + 2 * tig;
            *(float2*)&g_ao[(size_t)(i0 + row) * Dd + dcol] =
                make_float2(acc[ff][0], acc[ff][1]);
            *(float2*)&g_ao[(size_t)(i0 + row + 8) * Dd + dcol] =
                make_float2(acc[ff][2], acc[ff][3]);
        }
    }
}

// ---------------- launcher ------------------------------------------------
extern "C" void kernel_launch(void* const* d_in, const int* in_sizes, int n_in,
                              void* d_out, int out_size)
{
    (void)in_sizes; (void)n_in; (void)out_size;
    const float* x      = (const float*)d_in[0];
    const float* qkv_w  = (const float*)d_in[1];
    const float* qkv_b  = (const float*)d_in[2];
    const float* proj_w = (const float*)d_in[3];
    const float* proj_b = (const float*)d_in[4];
    const float* rel    = (const float*)d_in[5];
    float* out = (float*)d_out;

    cudaFuncSetAttribute(mma_gemm<0>, cudaFuncAttributeMaxDynamicSharedMemorySize,
                         GEMM_SMEM_BYTES);
    cudaFuncSetAttribute(mma_gemm<1>, cudaFuncAttributeMaxDynamicSharedMemorySize,
                         GEMM_SMEM_BYTES);
    cudaFuncSetAttribute(attn_kernel, cudaFuncAttributeMaxDynamicSharedMemorySize,
                         ATTN_SMEM_BYTES);

    // 1) packs: x (A-frags), qkv_w (B-frags), rel_emb (tf32, padded)
    packA<0><<<(Nn / 16) * (Dd / 8) * 32 / 256, 256>>>(x, Nn, Dd);
    packB<<<(3 * Dd / 8) * (Dd / 8) * 32 / 256, 256>>>(qkv_w, 3 * Dd, Dd);
    packE<<<Hh * 224 * HD / 256, 256>>>(rel);
    // 2) QKV GEMM: scatter q / k(scaled) / v as tf32
    mma_gemm<0><<<dim3(3 * Dd / 128, Nn / 128), 256, GEMM_SMEM_BYTES>>>(qkv_b,
                                                                        nullptr, Dd);
    // 3) fused pos + banded attention -> g_ao
    attn_kernel<<<dim3(Nn / QT, Hh), 512, ATTN_SMEM_BYTES>>>();
    // 4) pack g_ao (A-frags) and proj_w (B-frags)
    packA<1><<<(Nn / 16) * (Dd / 8) * 32 / 256, 256>>>(nullptr, Nn, Dd);
    packB<<<(Dd / 8) * (Dd / 8) * 32 / 256, 256>>>(proj_w, Dd, Dd);
    // 5) output projection -> d_out
    mma_gemm<1><<<dim3(Dd / 128, Nn / 128), 256, GEMM_SMEM_BYTES>>>(proj_b, out, Dd);
}

// round 11
// speedup vs baseline: 1.4332x; 1.0547x over previous
#include <cuda_runtime.h>
#include <cstdint>

#define Nn 2048
#define Dd 1024
#define Hh 16
#define HD 64
#define NEMB 199
#define RAD 99

// ---------------- scratch (device globals; no allocation) ----------------
__device__ float g_q[Hh * Nn * HD];        // tf32 bits
__device__ float g_k[Hh * Nn * HD];        // tf32 bits, pre-scaled by 1/8
__device__ float g_v[Hh * Nn * HD];        // tf32 bits
__device__ float g_Et[Hh * 224 * HD];      // tf32 rel_emb, zero-padded to 224 rows
__device__ float g_ao[Nn * Dd];
__device__ uint32_t g_Ap[Nn * Dd];         // packed A frags (tf32 bits)
__device__ uint32_t g_Bp[3 * Dd * Dd];     // packed B frags (tf32 bits)

// ---------------- common helpers ------------------------------------------
__device__ __forceinline__ uint32_t f2tf(float f) {
    uint32_t u;
    asm("cvt.rna.tf32.f32 %0, %1;" : "=r"(u) : "f"(f));
    return u;
}
__device__ __forceinline__ float f2tff(float f) {
    return __uint_as_float(f2tf(f));
}
__device__ __forceinline__ uint32_t smem_u32(const void* p) {
    uint32_t a;
    asm("{ .reg .u64 t; cvta.to.shared.u64 t, %1; cvt.u32.u64 %0, t; }"
        : "=r"(a) : "l"(p));
    return a;
}
__device__ __forceinline__ void cp16(uint32_t dst, const void* src) {
    asm volatile("cp.async.cg.shared.global [%0], [%1], 16;" :: "r"(dst), "l"(src) : "memory");
}

#define MMA_TF32(d, a0, a1, a2, a3, b0, b1) \
    asm volatile( \
        "mma.sync.aligned.m16n8k8.row.col.f32.tf32.tf32.f32 " \
        "{%0,%1,%2,%3}, {%4,%5,%6,%7}, {%8,%9}, {%0,%1,%2,%3};" \
        : "+f"((d)[0]), "+f"((d)[1]), "+f"((d)[2]), "+f"((d)[3]) \
        : "r"(a0), "r"(a1), "r"(a2), "r"(a3), "r"(b0), "r"(b1))

// ---------------- pack kernels: fp32 -> fragment-ready tf32 ----------------
template <int SRCAO>
__global__ void __launch_bounds__(256) packA(const float* __restrict__ src,
                                             int rows, int K)
{
    const float* in = SRCAO ? (const float*)g_ao : src;
    int idx = blockIdx.x * 256 + threadIdx.x;
    int KS = K >> 3;
    int total = (rows >> 4) * KS * 32;
    if (idx >= total) return;
    int lane = idx & 31;
    int ks = (idx >> 5) % KS;
    int mt = (idx >> 5) / KS;
    int gid = lane >> 2, tig = lane & 3;
    int r0 = mt * 16 + gid, c0 = ks * 8 + tig;
    uint4 o;
    o.x = f2tf(in[(size_t)r0 * K + c0]);
    o.y = f2tf(in[(size_t)(r0 + 8) * K + c0]);
    o.z = f2tf(in[(size_t)r0 * K + c0 + 4]);
    o.w = f2tf(in[(size_t)(r0 + 8) * K + c0 + 4]);
    *(uint4*)&g_Ap[(size_t)idx * 4] = o;
}

__global__ void __launch_bounds__(256) packB(const float* __restrict__ src,
                                             int rowsB, int K)
{
    int idx = blockIdx.x * 256 + threadIdx.x;
    int KS = K >> 3;
    int total = (rowsB >> 3) * KS * 32;
    if (idx >= total) return;
    int lane = idx & 31;
    int ks = (idx >> 5) % KS;
    int nt = (idx >> 5) / KS;
    int gid = lane >> 2, tig = lane & 3;
    int n = nt * 8 + gid, c0 = ks * 8 + tig;
    uint2 o;
    o.x = f2tf(src[(size_t)n * K + c0]);
    o.y = f2tf(src[(size_t)n * K + c0 + 4]);
    *(uint2*)&g_Bp[(size_t)idx * 2] = o;
}

// tf32 rel_emb, zero-padded rows [NEMB, 224)
__global__ void __launch_bounds__(256) packE(const float* __restrict__ rel)
{
    int idx = blockIdx.x * 256 + threadIdx.x;
    if (idx >= Hh * 224 * HD) return;
    int d = idx & 63;
    int r = (idx >> 6) % 224;
    int h = idx / (224 * 64);
    float v = 0.f;
    if (r < NEMB) v = f2tff(rel[((size_t)h * NEMB + r) * HD + d]);
    g_Et[idx] = v;
}

// ---------------- tf32 mma.sync GEMM, 3-stage cp.async --------------------
#define GEMM_SMEM_BYTES 98304

template <int MODE>
__global__ void __launch_bounds__(256, 2) mma_gemm(
    const float* __restrict__ bias, float* __restrict__ out, int K)
{
    extern __shared__ __align__(16) uint32_t smem[];
    uint32_t* sAm = smem;
    uint32_t* sBm = smem + 12288;
    const uint32_t sAu = smem_u32(sAm);
    const uint32_t sBu = smem_u32(sBm);

    const int t = threadIdx.x;
    const int KS = K >> 3;
    const int m0 = blockIdx.y * 128;
    const int n0 = blockIdx.x * 128;
    const int w = t >> 5, lane = t & 31;
    const int wy = w >> 2, wx = w & 3;
    const int gid = lane >> 2, tig = lane & 3;

    const uint32_t* Abase = g_Ap + (size_t)(blockIdx.y * 8) * KS * 128;
    const uint32_t* Bbase = g_Bp + (size_t)(blockIdx.x * 16) * KS * 64;

    float acc[4][4][4];
#pragma unroll
    for (int mi = 0; mi < 4; mi++)
#pragma unroll
        for (int ni = 0; ni < 4; ni++)
#pragma unroll
            for (int j = 0; j < 4; j++) acc[mi][ni][j] = 0.f;

    const int nc = K / 32;

    auto load_chunk = [&](int c, int s) {
        uint32_t ab = sAu + (uint32_t)s * 16384u;
        uint32_t bb = sBu + (uint32_t)s * 16384u;
#pragma unroll
        for (int q = 0; q < 4; q++) {
            int i4 = t + q * 256;
            int mt = i4 >> 7, rema = (i4 & 127) << 2;
            cp16(ab + (uint32_t)i4 * 16,
                 Abase + (size_t)mt * KS * 128 + c * 512 + rema);
            int nt = i4 >> 6, remb = (i4 & 63) << 2;
            cp16(bb + (uint32_t)i4 * 16,
                 Bbase + (size_t)nt * KS * 64 + c * 256 + remb);
        }
    };

    load_chunk(0, 0);
    asm volatile("cp.async.commit_group;" ::: "memory");
    load_chunk(1, 1);
    asm volatile("cp.async.commit_group;" ::: "memory");

    for (int c = 0; c < nc; ++c) {
        int s = c - (c / 3) * 3;
        asm volatile("cp.async.wait_group 1;" ::: "memory");
        __syncthreads();
        if (c + 2 < nc) {
            int s2 = (c + 2) - ((c + 2) / 3) * 3;
            load_chunk(c + 2, s2);
            asm volatile("cp.async.commit_group;" ::: "memory");
        } else {
            asm volatile("cp.async.commit_group;" ::: "memory");
        }

        const uint32_t* As = sAm + s * 4096;
        const uint32_t* Bs = sBm + s * 4096;
#pragma unroll
        for (int ksp = 0; ksp < 4; ksp++) {
            uint4 af[4];
            uint2 bf[4];
#pragma unroll
            for (int mi = 0; mi < 4; mi++)
                af[mi] = *(const uint4*)&As[(((wy * 4 + mi) * 4 + ksp) << 7) + (lane << 2)];
#pragma unroll
            for (int ni = 0; ni < 4; ni++)
                bf[ni] = *(const uint2*)&Bs[(((wx * 4 + ni) * 4 + ksp) << 6) + (lane << 1)];
#pragma unroll
            for (int mi = 0; mi < 4; mi++)
#pragma unroll
                for (int ni = 0; ni < 4; ni++)
                    MMA_TF32(acc[mi][ni], af[mi].x, af[mi].y, af[mi].z, af[mi].w,
                             bf[ni].x, bf[ni].y);
        }
    }

#pragma unroll
    for (int mi = 0; mi < 4; mi++) {
        int r0 = m0 + wy * 64 + mi * 16 + gid;
#pragma unroll
        for (int ni = 0; ni < 4; ni++) {
            int feat = n0 + wx * 32 + ni * 8 + 2 * tig;
            float2 bb = *(const float2*)&bias[feat];
            if (MODE == 0) {
                int sec = feat >> 10, hm = feat & 1023;
                float* p = (sec == 0) ? g_q : ((sec == 1) ? g_k : g_v);
                float sc = (sec == 1) ? 0.125f : 1.0f;
                int h = hm >> 6, d = hm & 63;
                // store tf32-rounded (consumed only by attn MMAs)
                float2 v0 = make_float2(f2tff((acc[mi][ni][0] + bb.x) * sc),
                                        f2tff((acc[mi][ni][1] + bb.y) * sc));
                float2 v1 = make_float2(f2tff((acc[mi][ni][2] + bb.x) * sc),
                                        f2tff((acc[mi][ni][3] + bb.y) * sc));
                *(float2*)&p[((h * Nn + r0) << 6) + d] = v0;
                *(float2*)&p[((h * Nn + r0 + 8) << 6) + d] = v1;
            } else {
                float2 v0 = make_float2(acc[mi][ni][0] + bb.x, acc[mi][ni][1] + bb.y);
                float2 v1 = make_float2(acc[mi][ni][2] + bb.x, acc[mi][ni][3] + bb.y);
                *(float2*)&out[(size_t)r0 * Dd + feat] = v0;
                *(float2*)&out[(size_t)(r0 + 8) * Dd + feat] = v1;
            }
        }
    }
}

// ---------------- fused banded attention + pos logits, 64q/512t ----------
// cp.async everywhere; Spos held in regs, merged into band-relative S.
#define QT 64
#define BND 288
#define ERWS 224
#define BP 68
#define SSP2 244           // band-relative S pitch
#define SQ_F (QT * BP)                 // 4352
#define SE_F (ERWS * BP)               // 15232
#define SB_F (BND * BP)                // 19584
#define SS_F (QT * SSP2)               // 15616
#define ATTN_SMEM_BYTES ((SQ_F + SE_F + SB_F + SS_F) * 4)   // 219136

__global__ void __launch_bounds__(512) attn_kernel()
{
    extern __shared__ __align__(16) float sm[];
    float* sQ = sm;                    // [64][BP]
    float* sE = sm + SQ_F;             // [224][BP]
    float* sB = sm + SQ_F + SE_F;      // [288][BP]: K -> V
    float* sS = sm + SQ_F + SE_F + SB_F; // [64][SSP2] band-relative S/P
    const uint32_t sQu = smem_u32(sQ);
    const uint32_t sEu = smem_u32(sE);
    const uint32_t sBu = smem_u32(sB);

    const int h = blockIdx.y;
    const int i0 = blockIdx.x * QT;
    const int jlo = i0 - RAD;
    const int t = threadIdx.x;
    const int w = t >> 5, lane = t & 31;
    const int gid = lane >> 2, tig = lane & 3;
    const int mw = w & 3, nw = w >> 2;

    // ---- issue Q + E cp.async (group A) ----
    const float* Qg = g_q + ((size_t)(h * Nn + i0) << 6);
    for (int idx = t; idx < QT * 16; idx += 512) {
        int qi = idx >> 4, d4 = (idx & 15) << 2;
        cp16(sQu + (uint32_t)(qi * BP + d4) * 4, Qg + (qi << 6) + d4);
    }
    const float* Eg = g_Et + (size_t)h * ERWS * HD;
    for (int idx = t; idx < ERWS * 16; idx += 512) {
        int r = idx >> 4, d4 = (idx & 15) << 2;
        cp16(sEu + (uint32_t)(r * BP + d4) * 4, Eg + r * HD + d4);
    }
    asm volatile("cp.async.commit_group;" ::: "memory");

    // ---- issue K band cp.async (group B), zero-fill invalid rows ----
    for (int idx = t; idx < BND * 16; idx += 512) {
        int jj = idx >> 4, d4 = (idx & 15) << 2;
        int j = jlo + jj;
        if (j >= 0 && j < Nn)
            cp16(sBu + (uint32_t)(jj * BP + d4) * 4,
                 g_k + (((size_t)(h * Nn) + j) << 6) + d4);
        else
            *(float4*)&sB[jj * BP + d4] = make_float4(0.f, 0.f, 0.f, 0.f);
    }
    asm volatile("cp.async.commit_group;" ::: "memory");

    asm volatile("cp.async.wait_group 1;" ::: "memory");
    __syncthreads();

    // ---- Spos = Q @ E^T, accumulators kept in registers ----
    float pacc[7][4];
#pragma unroll
    for (int f = 0; f < 7; f++)
#pragma unroll
        for (int j = 0; j < 4; j++) pacc[f][j] = 0.f;
#pragma unroll
    for (int ks = 0; ks < 8; ks++) {
        int kb = ks * 8 + tig;
        uint32_t a0 = __float_as_uint(sQ[(mw * 16 + gid) * BP + kb]);
        uint32_t a1 = __float_as_uint(sQ[(mw * 16 + gid + 8) * BP + kb]);
        uint32_t a2 = __float_as_uint(sQ[(mw * 16 + gid) * BP + kb + 4]);
        uint32_t a3 = __float_as_uint(sQ[(mw * 16 + gid + 8) * BP + kb + 4]);
#pragma unroll
        for (int f = 0; f < 7; f++) {
            int nb = (nw * 7 + f) * 8;
            uint32_t b0 = __float_as_uint(sE[(nb + gid) * BP + kb]);
            uint32_t b1 = __float_as_uint(sE[(nb + gid) * BP + kb + 4]);
            MMA_TF32(pacc[f], a0, a1, a2, a3, b0, b1);
        }
    }

    asm volatile("cp.async.wait_group 0;" ::: "memory");
    __syncthreads();

    // ---- Sqk band-restricted -> store band-relative: local col = jj - 16mw --
    {
        float acc[7][4];
#pragma unroll
        for (int f = 0; f < 7; f++)
#pragma unroll
            for (int j = 0; j < 4; j++) acc[f][j] = 0.f;
#pragma unroll
        for (int ks = 0; ks < 8; ks++) {
            int kb = ks * 8 + tig;
            uint32_t a0 = __float_as_uint(sQ[(mw * 16 + gid) * BP + kb]);
            uint32_t a1 = __float_as_uint(sQ[(mw * 16 + gid + 8) * BP + kb]);
            uint32_t a2 = __float_as_uint(sQ[(mw * 16 + gid) * BP + kb + 4]);
            uint32_t a3 = __float_as_uint(sQ[(mw * 16 + gid + 8) * BP + kb + 4]);
#pragma unroll
            for (int f = 0; f < 7; f++) {
                int nb = (2 * mw + nw * 7 + f) * 8;
                uint32_t b0 = __float_as_uint(sB[(nb + gid) * BP + kb]);
                uint32_t b1 = __float_as_uint(sB[(nb + gid) * BP + kb + 4]);
                MMA_TF32(acc[f], a0, a1, a2, a3, b0, b1);
            }
        }
        int r0 = mw * 16 + gid;
#pragma unroll
        for (int f = 0; f < 7; f++) {
            int col = (nw * 7 + f) * 8 + 2 * tig;   // local = global - 16mw
            *(float2*)&sS[r0 * SSP2 + col] = make_float2(acc[f][0], acc[f][1]);
            *(float2*)&sS[(r0 + 8) * SSP2 + col] = make_float2(acc[f][2], acc[f][3]);
        }
    }
    __syncthreads();

    // ---- issue V band cp.async (overwrites sB) ----
    for (int idx = t; idx < BND * 16; idx += 512) {
        int jj = idx >> 4, d4 = (idx & 15) << 2;
        int j = jlo + jj;
        if (j >= 0 && j < Nn)
            cp16(sBu + (uint32_t)(jj * BP + d4) * 4,
                 g_v + (((size_t)(h * Nn) + j) << 6) + d4);
        else
            *(float4*)&sB[jj * BP + d4] = make_float4(0.f, 0.f, 0.f, 0.f);
    }
    asm volatile("cp.async.commit_group;" ::: "memory");

    // ---- merge pos into S (scalar: diagonal shift makes offsets odd) ----
    {
        int rl0 = gid, rl1 = gid + 8;          // local rows within m-tile mw
        int q0 = mw * 16 + gid, q1 = q0 + 8;   // tile rows
#pragma unroll
        for (int f = 0; f < 7; f++) {
            int r = (nw * 7 + f) * 8 + 2 * tig;
            float* p0 = &sS[q0 * SSP2 + rl0 + r];
            p0[0] += pacc[f][0];
            p0[1] += pacc[f][1];
            float* p1 = &sS[q1 * SSP2 + rl1 + r];
            p1[0] += pacc[f][2];
            p1[1] += pacc[f][3];
        }
    }
    __syncthreads();

    // ---- banded softmax, 4 rows/warp ILP; P written as tf32 ----
    {
        float v[4][7];
#pragma unroll
        for (int p = 0; p < 4; p++) {
            int qi = w * 4 + p;
            int ql = qi & 15;
            int i = i0 + qi;
#pragma unroll
            for (int u = 0; u < 7; u++) {
                int r = lane + u * 32;
                float val = -1e30f;
                if (r < NEMB) {
                    int j = i - RAD + r;
                    if (j >= 0 && j < Nn)
                        val = sS[qi * SSP2 + ql + r];
                }
                v[p][u] = val;
            }
        }
        float mx[4];
#pragma unroll
        for (int p = 0; p < 4; p++) {
            mx[p] = v[p][0];
#pragma unroll
            for (int u = 1; u < 7; u++) mx[p] = fmaxf(mx[p], v[p][u]);
        }
#pragma unroll
        for (int off = 16; off; off >>= 1)
#pragma unroll
            for (int p = 0; p < 4; p++)
                mx[p] = fmaxf(mx[p], __shfl_xor_sync(0xffffffffu, mx[p], off));
        float s[4] = {0.f, 0.f, 0.f, 0.f};
#pragma unroll
        for (int p = 0; p < 4; p++)
#pragma unroll
            for (int u = 0; u < 7; u++) {
                v[p][u] = (v[p][u] > -1e29f) ? __expf(v[p][u] - mx[p]) : 0.f;
                s[p] += v[p][u];
            }
#pragma unroll
        for (int off = 16; off; off >>= 1)
#pragma unroll
            for (int p = 0; p < 4; p++)
                s[p] += __shfl_xor_sync(0xffffffffu, s[p], off);
        float inv[4];
#pragma unroll
        for (int p = 0; p < 4; p++) inv[p] = 1.f / s[p];

        // zero cols [0,224), then write normalized P at band positions
#pragma unroll
        for (int p = 0; p < 4; p++) {
            int qi = w * 4 + p;
#pragma unroll
            for (int u = 0; u < 7; u++)
                sS[qi * SSP2 + lane + u * 32] = 0.f;
        }
        __syncwarp();
#pragma unroll
        for (int p = 0; p < 4; p++) {
            int qi = w * 4 + p;
            int ql = qi & 15;
#pragma unroll
            for (int u = 0; u < 7; u++) {
                int r = lane + u * 32;
                if (r < NEMB && v[p][u] != 0.f)
                    sS[qi * SSP2 + ql + r] = f2tff(v[p][u] * inv[p]);
            }
        }
    }
    asm volatile("cp.async.wait_group 0;" ::: "memory");
    __syncthreads();

    // ---- O = P @ V (band-relative): A cols [0,216), B rows 16mw + kb ----
    {
        float acc[2][4];
#pragma unroll
        for (int ff = 0; ff < 2; ff++)
#pragma unroll
            for (int j = 0; j < 4; j++) acc[ff][j] = 0.f;

#pragma unroll
        for (int ks = 0; ks < 27; ks++) {
            int kb = ks * 8 + tig;
            uint32_t a0 = __float_as_uint(sS[(mw * 16 + gid) * SSP2 + kb]);
            uint32_t a1 = __float_as_uint(sS[(mw * 16 + gid + 8) * SSP2 + kb]);
            uint32_t a2 = __float_as_uint(sS[(mw * 16 + gid) * SSP2 + kb + 4]);
            uint32_t a3 = __float_as_uint(sS[(mw * 16 + gid + 8) * SSP2 + kb + 4]);
            int vrow = mw * 16 + kb;
#pragma unroll
            for (int ff = 0; ff < 2; ff++) {
                int nd = (nw * 2 + ff) * 8 + gid;
                uint32_t b0 = __float_as_uint(sB[vrow * BP + nd]);
                uint32_t b1 = __float_as_uint(sB[(vrow + 4) * BP + nd]);
                MMA_TF32(acc[ff], a0, a1, a2, a3, b0, b1);
            }
        }
        int row = mw * 16 + gid;
#pragma unroll
        for (int ff = 0; ff < 2; ff++) {
            int dcol = h * 64 + (nw * 2 + ff) * 8 + 2 * tig;
            *(float2*)&g_ao[(size_t)(i0 + row) * Dd + dcol] =
                make_float2(acc[ff][0], acc[ff][1]);
            *(float2*)&g_ao[(size_t)(i0 + row + 8) * Dd + dcol] =
                make_float2(acc[ff][2], acc[ff][3]);
        }
    }
}

// ---------------- launcher ------------------------------------------------
extern "C" void kernel_launch(void* const* d_in, const int* in_sizes, int n_in,
                              void* d_out, int out_size)
{
    (void)in_sizes; (void)n_in; (void)out_size;
    const float* x      = (const float*)d_in[0];
    const float* qkv_w  = (const float*)d_in[1];
    const float* qkv_b  = (const float*)d_in[2];
    const float* proj_w = (const float*)d_in[3];
    const float* proj_b = (const float*)d_in[4];
    const float* rel    = (const float*)d_in[5];
    float* out = (float*)d_out;

    cudaFuncSetAttribute(mma_gemm<0>, cudaFuncAttributeMaxDynamicSharedMemorySize,
                         GEMM_SMEM_BYTES);
    cudaFuncSetAttribute(mma_gemm<1>, cudaFuncAttributeMaxDynamicSharedMemorySize,
                         GEMM_SMEM_BYTES);
    cudaFuncSetAttribute(attn_kernel, cudaFuncAttributeMaxDynamicSharedMemorySize,
                         ATTN_SMEM_BYTES);

    // 1) packs: x (A-frags), qkv_w (B-frags), rel_emb (tf32, padded)
    packA<0><<<(Nn / 16) * (Dd / 8) * 32 / 256, 256>>>(x, Nn, Dd);
    packB<<<(3 * Dd / 8) * (Dd / 8) * 32 / 256, 256>>>(qkv_w, 3 * Dd, Dd);
    packE<<<Hh * 224 * HD / 256, 256>>>(rel);
    // 2) QKV GEMM: scatter q / k(scaled) / v as tf32
    mma_gemm<0><<<dim3(3 * Dd / 128, Nn / 128), 256, GEMM_SMEM_BYTES>>>(qkv_b,
                                                                        nullptr, Dd);
    // 3) fused pos + banded attention -> g_ao
    attn_kernel<<<dim3(Nn / QT, Hh), 512, ATTN_SMEM_BYTES>>>();
    // 4) pack g_ao (A-frags) and proj_w (B-frags)
    packA<1><<<(Nn / 16) * (Dd / 8) * 32 / 256, 256>>>(nullptr, Nn, Dd);
    packB<<<(Dd / 8) * (Dd / 8) * 32 / 256, 256>>>(proj_w, Dd, Dd);
    // 5) output projection -> d_out
    mma_gemm<1><<<dim3(Dd / 128, Nn / 128), 256, GEMM_SMEM_BYTES>>>(proj_b, out, Dd);
}